// round 3
// baseline (speedup 1.0000x reference)
#include <cuda_runtime.h>
#include <math.h>

#define NN 50000
#define EE 800000
#define TT 8
#define RR 8
#define NB_SCAN 196   // ceil(NN/256)

// ---------------- scratch (static device memory; no allocations) ----------------
__device__ int   g_is64_adj, g_is64_et, g_is64_nt;
__device__ float g_Wqa[TT*64*512];              // 1 MB: Wq[t] @ A_r^T, r-concat
__device__ float g_Wma[TT*512*64];              // 1 MB: Mstack @ Wa[t]
__device__ float g_knode[(size_t)NN*64];        // 12.8 MB (permuted order)
__device__ float g_vnode[(size_t)NN*64];        // 12.8 MB (permuted order)
__device__ float g_qrel[(size_t)NN*512];        // 102.4 MB (permuted order)
__device__ float g_bucket[(size_t)NN*512];      // 102.4 MB (permuted order)
__device__ int   g_perm[NN];
__device__ int   g_iperm[NN];
__device__ int   g_deg[NN];
__device__ int   g_cursor[NN];
__device__ int   g_rowptr[NN+1];
__device__ int   g_bsum[256];
__device__ int   g_boff[256];
__device__ int   g_tcount[TT];
__device__ int   g_tbase[TT];
__device__ int   g_tcur[TT];
__device__ int   g_csr[EE];                     // src_pos | (r<<20)

__device__ __forceinline__ int ld_idx(const void* p, long i, int is64) {
    if (is64) return (int)(((const long long*)p)[i]);
    return ((const int*)p)[i];
}

// ---------------- dtype detection ----------------
__global__ void k_detect(const void* adj, const void* et, const void* nt) {
    if (threadIdx.x != 0 || blockIdx.x != 0) return;
    int a = 1, b = 1, c = 1;
    for (int i = 0; i < 128; i++) if (((const int*)adj)[2*(i*1000)+1]) { a = 0; break; }
    for (int i = 0; i < 128; i++) if (((const int*)et )[2*(i*3000)+1]) { b = 0; break; }
    for (int i = 0; i < 128; i++) if (((const int*)nt )[2*(i*150 )+1]) { c = 0; break; }
    g_is64_adj = a; g_is64_et = b; g_is64_nt = c;
}

__global__ void k_zero() {
    int i = blockIdx.x*blockDim.x + threadIdx.x;
    if (i < NN) { g_deg[i] = 0; g_cursor[i] = 0; }
    if (i < TT) { g_tcount[i] = 0; g_tcur[i] = 0; }
    if (i == 0) g_rowptr[NN] = EE;
}

// ---------------- node counting sort by type ----------------
__global__ void k_nhist(const void* nt) {
    int i = blockIdx.x*blockDim.x + threadIdx.x;
    if (i >= NN) return;
    atomicAdd(&g_tcount[ld_idx(nt, i, g_is64_nt)], 1);
}
__global__ void k_tscan() {
    if (threadIdx.x == 0 && blockIdx.x == 0) {
        int s = 0;
        for (int t = 0; t < TT; t++) { g_tbase[t] = s; s += g_tcount[t]; }
    }
}
__global__ void k_nscatter(const void* nt) {
    int i = blockIdx.x*blockDim.x + threadIdx.x;
    if (i >= NN) return;
    int t = ld_idx(nt, i, g_is64_nt);
    int p = g_tbase[t] + atomicAdd(&g_tcur[t], 1);
    g_perm[p] = i;
}
__global__ void k_iperm() {
    int i = blockIdx.x*blockDim.x + threadIdx.x;
    if (i >= NN) return;
    g_iperm[g_perm[i]] = i;
}

// ---------------- CSR build over permuted dst ----------------
__global__ void k_ehist(const void* adj) {
    int e = blockIdx.x*blockDim.x + threadIdx.x;
    if (e >= EE) return;
    int d = ld_idx(adj, (long)EE + e, g_is64_adj);
    atomicAdd(&g_deg[g_iperm[d]], 1);
}
__global__ void k_scanA() {
    __shared__ int s[256];
    int i = blockIdx.x*256 + threadIdx.x;
    int v = (i < NN) ? g_deg[i] : 0;
    s[threadIdx.x] = v; __syncthreads();
    for (int off = 1; off < 256; off <<= 1) {
        int t = (threadIdx.x >= off) ? s[threadIdx.x - off] : 0;
        __syncthreads();
        s[threadIdx.x] += t;
        __syncthreads();
    }
    if (i < NN) g_rowptr[i] = s[threadIdx.x] - v;
    if (threadIdx.x == 255) g_bsum[blockIdx.x] = s[255];
}
__global__ void k_scanB() {
    __shared__ int s[256];
    int i = threadIdx.x;
    int v = (i < NB_SCAN) ? g_bsum[i] : 0;
    s[i] = v; __syncthreads();
    for (int off = 1; off < 256; off <<= 1) {
        int t = (i >= off) ? s[i - off] : 0;
        __syncthreads();
        s[i] += t;
        __syncthreads();
    }
    g_boff[i] = s[i] - v;
}
__global__ void k_scanC() {
    int i = blockIdx.x*256 + threadIdx.x;
    if (i < NN) g_rowptr[i] += g_boff[blockIdx.x];
}
__global__ void k_escatter(const void* adj, const void* et) {
    int e = blockIdx.x*blockDim.x + threadIdx.x;
    if (e >= EE) return;
    int sflag = g_is64_adj;
    int src = ld_idx(adj, e, sflag);
    int dst = ld_idx(adj, (long)EE + e, sflag);
    int r   = ld_idx(et, e, g_is64_et);
    int dp = g_iperm[dst];
    int sp = g_iperm[src];
    int p = g_rowptr[dp] + atomicAdd(&g_cursor[dp], 1);
    g_csr[p] = sp | (r << 20);
}

// ---------------- weight folds ----------------
// Wqa[t][m][r*64+i] = sum_j qw[t][m][j] * att[r][i][j]
__global__ void k_fold_qa(const float* __restrict__ qw, const float* __restrict__ att) {
    __shared__ float sQ[4096], sT[4096];
    int b = blockIdx.x; int t = b >> 3, r = b & 7;
    int tid = threadIdx.x;
    for (int e = tid; e < 1024; e += 256) {
        ((float4*)sQ)[e] = ((const float4*)(qw + t*4096))[e];
        ((float4*)sT)[e] = ((const float4*)(att + r*4096))[e];
    }
    __syncthreads();
    int i = tid & 63, mg = (tid >> 6) * 16;
    float acc[16];
    #pragma unroll
    for (int u = 0; u < 16; u++) acc[u] = 0.f;
    for (int j = 0; j < 64; j++) {
        float bv = sT[i*64 + j];
        #pragma unroll
        for (int u = 0; u < 16; u++) acc[u] += sQ[(mg+u)*64 + j] * bv;
    }
    #pragma unroll
    for (int u = 0; u < 16; u++)
        g_Wqa[t*32768 + (mg+u)*512 + r*64 + i] = acc[u];
}
// Wma[t][r*64+i][j] = sum_c msg[r][i][c] * aw[t][c][j]
__global__ void k_fold_ma(const float* __restrict__ msg, const float* __restrict__ aw) {
    __shared__ float sM[4096], sW[4096];
    int b = blockIdx.x; int t = b >> 3, r = b & 7;
    int tid = threadIdx.x;
    for (int e = tid; e < 1024; e += 256) {
        ((float4*)sM)[e] = ((const float4*)(msg + r*4096))[e];
        ((float4*)sW)[e] = ((const float4*)(aw + t*4096))[e];
    }
    __syncthreads();
    int j = tid & 63, ig = (tid >> 6) * 16;
    float acc[16];
    #pragma unroll
    for (int u = 0; u < 16; u++) acc[u] = 0.f;
    for (int c = 0; c < 64; c++) {
        float bv = sW[c*64 + j];
        #pragma unroll
        for (int u = 0; u < 16; u++) acc[u] += sM[(ig+u)*64 + c] * bv;
    }
    #pragma unroll
    for (int u = 0; u < 16; u++)
        g_Wma[t*32768 + (r*64 + ig+u)*64 + j] = acc[u];
}

// ---------------- k_node/v_node typed GEMM: 128 nodes x 64 cols, tile 8x4 ----------------
__global__ void k_kv(const float* __restrict__ h, const float* __restrict__ kw,
                     const float* __restrict__ vw, const void* nt) {
    extern __shared__ float sm[];
    float* sA  = sm;            // 64*128 (h transposed)
    float* sWk = sA + 8192;     // 4096
    float* sWv = sWk + 4096;    // 4096
    int* sNode = (int*)(sWv + 4096);
    int* sTy   = sNode + 128;
    int tid = threadIdx.x;
    int base = blockIdx.x * 128;
    if (tid < 128) {
        int idx = base + tid; if (idx > NN-1) idx = NN-1;
        int node = g_perm[idx];
        sNode[tid] = node;
        sTy[tid] = ld_idx(nt, node, g_is64_nt);
    }
    __syncthreads();
    {
        int m = tid >> 1, half = tid & 1;
        const float4* hp = (const float4*)(h + (size_t)sNode[m]*64 + half*32);
        #pragma unroll
        for (int j = 0; j < 8; j++) {
            float4 v = hp[j];
            int k0 = half*32 + j*4;
            sA[(k0+0)*128 + m] = v.x;
            sA[(k0+1)*128 + m] = v.y;
            sA[(k0+2)*128 + m] = v.z;
            sA[(k0+3)*128 + m] = v.w;
        }
    }
    __syncthreads();
    int t0 = sTy[0], t1 = sTy[127];
    int wy = tid >> 4, wx = tid & 15;
    int m0 = wy*8, c0 = wx*4;
    for (int t = t0; t <= t1; t++) {
        for (int e = tid; e < 1024; e += 256) {
            ((float4*)sWk)[e] = ((const float4*)(kw + t*4096))[e];
            ((float4*)sWv)[e] = ((const float4*)(vw + t*4096))[e];
        }
        __syncthreads();
        float aK[8][4], aV[8][4];
        #pragma unroll
        for (int i = 0; i < 8; i++)
            #pragma unroll
            for (int j = 0; j < 4; j++) { aK[i][j] = 0.f; aV[i][j] = 0.f; }
        #pragma unroll 4
        for (int k = 0; k < 64; k++) {
            float4 bk = *(const float4*)&sWk[k*64 + c0];
            float4 bv = *(const float4*)&sWv[k*64 + c0];
            float4 a0 = *(const float4*)&sA[k*128 + m0];
            float4 a1 = *(const float4*)&sA[k*128 + m0 + 4];
            float av[8] = {a0.x,a0.y,a0.z,a0.w,a1.x,a1.y,a1.z,a1.w};
            #pragma unroll
            for (int i = 0; i < 8; i++) {
                aK[i][0] += av[i]*bk.x; aK[i][1] += av[i]*bk.y;
                aK[i][2] += av[i]*bk.z; aK[i][3] += av[i]*bk.w;
                aV[i][0] += av[i]*bv.x; aV[i][1] += av[i]*bv.y;
                aV[i][2] += av[i]*bv.z; aV[i][3] += av[i]*bv.w;
            }
        }
        #pragma unroll
        for (int i = 0; i < 8; i++) {
            int row = m0 + i, idx = base + row;
            if (idx < NN && sTy[row] == t) {
                *(float4*)&g_knode[(size_t)idx*64 + c0] = make_float4(aK[i][0],aK[i][1],aK[i][2],aK[i][3]);
                *(float4*)&g_vnode[(size_t)idx*64 + c0] = make_float4(aV[i][0],aV[i][1],aV[i][2],aV[i][3]);
            }
        }
        __syncthreads();
    }
}

// ---------------- q_rel GEMM: out[pos][512] = h[perm] @ Wqa[t]; 128x128 tiles, 8x8 ----------------
__global__ void k_qrel(const float* __restrict__ h, const void* nt) {
    extern __shared__ float sm[];
    float* sA = sm;            // 64*128 (h transposed)
    float* sB = sA + 8192;     // 64*128 (W slice)
    int* sNode = (int*)(sB + 8192);
    int* sTy   = sNode + 128;
    int tid = threadIdx.x;
    int base = blockIdx.x * 128;
    int col0 = blockIdx.y * 128;
    if (tid < 128) {
        int idx = base + tid; if (idx > NN-1) idx = NN-1;
        int node = g_perm[idx];
        sNode[tid] = node;
        sTy[tid] = ld_idx(nt, node, g_is64_nt);
    }
    __syncthreads();
    {
        int m = tid >> 1, half = tid & 1;
        const float4* hp = (const float4*)(h + (size_t)sNode[m]*64 + half*32);
        #pragma unroll
        for (int j = 0; j < 8; j++) {
            float4 v = hp[j];
            int k0 = half*32 + j*4;
            sA[(k0+0)*128 + m] = v.x;
            sA[(k0+1)*128 + m] = v.y;
            sA[(k0+2)*128 + m] = v.z;
            sA[(k0+3)*128 + m] = v.w;
        }
    }
    __syncthreads();
    int t0 = sTy[0], t1 = sTy[127];
    int wy = tid >> 4, wx = tid & 15;
    int m0 = wy*8, n0 = wx*8;
    for (int t = t0; t <= t1; t++) {
        for (int e = tid; e < 2048; e += 256) {
            int k = e >> 5, n4 = e & 31;
            ((float4*)&sB[k*128])[n4] = *(const float4*)&g_Wqa[t*32768 + k*512 + col0 + n4*4];
        }
        __syncthreads();
        float acc[8][8];
        #pragma unroll
        for (int i = 0; i < 8; i++)
            #pragma unroll
            for (int j = 0; j < 8; j++) acc[i][j] = 0.f;
        #pragma unroll 2
        for (int k = 0; k < 64; k++) {
            float4 a0 = *(const float4*)&sA[k*128 + m0];
            float4 a1 = *(const float4*)&sA[k*128 + m0 + 4];
            float4 b0 = *(const float4*)&sB[k*128 + n0];
            float4 b1 = *(const float4*)&sB[k*128 + n0 + 4];
            float av[8] = {a0.x,a0.y,a0.z,a0.w,a1.x,a1.y,a1.z,a1.w};
            float bv[8] = {b0.x,b0.y,b0.z,b0.w,b1.x,b1.y,b1.z,b1.w};
            #pragma unroll
            for (int i = 0; i < 8; i++)
                #pragma unroll
                for (int j = 0; j < 8; j++) acc[i][j] += av[i]*bv[j];
        }
        #pragma unroll
        for (int i = 0; i < 8; i++) {
            int row = m0 + i, idx = base + row;
            if (idx < NN && sTy[row] == t) {
                *(float4*)&g_qrel[(size_t)idx*512 + col0 + n0]     = make_float4(acc[i][0],acc[i][1],acc[i][2],acc[i][3]);
                *(float4*)&g_qrel[(size_t)idx*512 + col0 + n0 + 4] = make_float4(acc[i][4],acc[i][5],acc[i][6],acc[i][7]);
            }
        }
        __syncthreads();
    }
}

// ---------------- fused edge phase: warp per dst, online softmax, reg buckets ----------------
__global__ void k_edge(const float* __restrict__ pri) {
    int d = blockIdx.x*8 + (threadIdx.x >> 5);
    if (d >= NN) return;
    int lane = threadIdx.x & 31;
    float2 q[8];
    float pr[8];
    #pragma unroll
    for (int r = 0; r < 8; r++) {
        q[r] = *(const float2*)&g_qrel[(size_t)d*512 + r*64 + lane*2];
        pr[r] = pri[r] * 0.125f;
    }
    int rs = g_rowptr[d], re = g_rowptr[d+1];
    float m = -3.0e38f, s = 0.f;
    float2 b[8];
    #pragma unroll
    for (int r = 0; r < 8; r++) b[r] = make_float2(0.f, 0.f);
    for (int p = rs; p < re; p++) {
        int pk = g_csr[p];
        int sp = pk & 0xFFFFF;
        int r  = pk >> 20;
        float2 kv = *(const float2*)&g_knode[(size_t)sp*64 + lane*2];
        float2 qs = q[0]; float prs = pr[0];
        #pragma unroll
        for (int rr = 1; rr < 8; rr++) if (r == rr) { qs = q[rr]; prs = pr[rr]; }
        float part = kv.x*qs.x + kv.y*qs.y;
        part += __shfl_xor_sync(0xFFFFFFFFu, part, 16);
        part += __shfl_xor_sync(0xFFFFFFFFu, part, 8);
        part += __shfl_xor_sync(0xFFFFFFFFu, part, 4);
        part += __shfl_xor_sync(0xFFFFFFFFu, part, 2);
        part += __shfl_xor_sync(0xFFFFFFFFu, part, 1);
        float score = part * prs;
        float2 vv = *(const float2*)&g_vnode[(size_t)sp*64 + lane*2];
        if (score > m) {
            float c = __expf(m - score);
            s *= c;
            #pragma unroll
            for (int rr = 0; rr < 8; rr++) { b[rr].x *= c; b[rr].y *= c; }
            m = score;
        }
        float w = __expf(score - m);
        s += w;
        #pragma unroll
        for (int rr = 0; rr < 8; rr++) if (r == rr) { b[rr].x += w*vv.x; b[rr].y += w*vv.y; }
    }
    float inv = 1.0f / (s + 1e-16f);
    #pragma unroll
    for (int r = 0; r < 8; r++)
        *(float2*)&g_bucket[(size_t)d*512 + r*64 + lane*2] = make_float2(b[r].x*inv, b[r].y*inv);
}

// ---------------- output GEMM: out[node] = bucket[pos][512] @ Wma[t] * sigmoid(skip[t]) ----------------
__global__ void k_out(float* __restrict__ out, const float* __restrict__ skip, const void* nt) {
    extern __shared__ float sm[];
    float* sA = sm;            // 64*128 (bucket chunk, transposed)
    float* sW = sA + 8192;     // 64*64
    int* sNode = (int*)(sW + 4096);
    int* sTy   = sNode + 128;
    int tid = threadIdx.x;
    int base = blockIdx.x * 128;
    if (tid < 128) {
        int idx = base + tid; if (idx > NN-1) idx = NN-1;
        int node = g_perm[idx];
        sNode[tid] = node;
        sTy[tid] = ld_idx(nt, node, g_is64_nt);
    }
    __syncthreads();
    int t0 = sTy[0], t1 = sTy[127];
    int wy = tid >> 4, wx = tid & 15;
    int m0 = wy*8, c0 = wx*4;
    int mload = tid >> 1, half = tid & 1;
    int posl = base + mload; if (posl > NN-1) posl = NN-1;
    for (int t = t0; t <= t1; t++) {
        float acc[8][4];
        #pragma unroll
        for (int i = 0; i < 8; i++)
            #pragma unroll
            for (int j = 0; j < 4; j++) acc[i][j] = 0.f;
        for (int kk = 0; kk < 8; kk++) {
            {
                const float4* bp = (const float4*)&g_bucket[(size_t)posl*512 + kk*64 + half*32];
                #pragma unroll
                for (int j = 0; j < 8; j++) {
                    float4 v = bp[j];
                    int k0 = half*32 + j*4;
                    sA[(k0+0)*128 + mload] = v.x;
                    sA[(k0+1)*128 + mload] = v.y;
                    sA[(k0+2)*128 + mload] = v.z;
                    sA[(k0+3)*128 + mload] = v.w;
                }
            }
            for (int e = tid; e < 1024; e += 256)
                ((float4*)sW)[e] = ((const float4*)&g_Wma[t*32768 + kk*4096])[e];
            __syncthreads();
            #pragma unroll 4
            for (int k = 0; k < 64; k++) {
                float4 bw = *(const float4*)&sW[k*64 + c0];
                float4 a0 = *(const float4*)&sA[k*128 + m0];
                float4 a1 = *(const float4*)&sA[k*128 + m0 + 4];
                float av[8] = {a0.x,a0.y,a0.z,a0.w,a1.x,a1.y,a1.z,a1.w};
                #pragma unroll
                for (int i = 0; i < 8; i++) {
                    acc[i][0] += av[i]*bw.x; acc[i][1] += av[i]*bw.y;
                    acc[i][2] += av[i]*bw.z; acc[i][3] += av[i]*bw.w;
                }
            }
            __syncthreads();
        }
        float sc = 1.0f / (1.0f + __expf(-skip[t]));
        #pragma unroll
        for (int i = 0; i < 8; i++) {
            int row = m0 + i, idx = base + row;
            if (idx < NN && sTy[row] == t) {
                *(float4*)&out[(size_t)sNode[row]*64 + c0] =
                    make_float4(acc[i][0]*sc, acc[i][1]*sc, acc[i][2]*sc, acc[i][3]*sc);
            }
        }
    }
}

// ---------------- launch ----------------
extern "C" void kernel_launch(void* const* d_in, const int* in_sizes, int n_in,
                              void* d_out, int out_size) {
    const float* h   = (const float*)d_in[0];
    const void*  adj = d_in[1];
    const void*  et  = d_in[2];
    const void*  nt  = d_in[3];
    int off = n_in - 8;
    const float* kw   = (const float*)d_in[off + 0];
    const float* qw   = (const float*)d_in[off + 1];
    const float* vw   = (const float*)d_in[off + 2];
    const float* aw   = (const float*)d_in[off + 3];
    const float* pri  = (const float*)d_in[off + 4];
    const float* att  = (const float*)d_in[off + 5];
    const float* msg  = (const float*)d_in[off + 6];
    const float* skip = (const float*)d_in[off + 7];
    float* out = (float*)d_out;

    const int SM_KV   = (8192 + 4096 + 4096)*4 + 256*4 + 16;
    const int SM_QREL = (8192 + 8192)*4 + 256*4 + 16;
    const int SM_OUT  = (8192 + 4096)*4 + 256*4 + 16;
    cudaFuncSetAttribute(k_kv,   cudaFuncAttributeMaxDynamicSharedMemorySize, SM_KV);
    cudaFuncSetAttribute(k_qrel, cudaFuncAttributeMaxDynamicSharedMemorySize, SM_QREL);
    cudaFuncSetAttribute(k_out,  cudaFuncAttributeMaxDynamicSharedMemorySize, SM_OUT);

    k_detect<<<1, 1>>>(adj, et, nt);
    k_zero<<<(NN + 255)/256, 256>>>();
    k_nhist<<<(NN + 255)/256, 256>>>(nt);
    k_tscan<<<1, 1>>>();
    k_nscatter<<<(NN + 255)/256, 256>>>(nt);
    k_iperm<<<(NN + 255)/256, 256>>>();
    k_ehist<<<(EE + 255)/256, 256>>>(adj);
    k_scanA<<<NB_SCAN, 256>>>();
    k_scanB<<<1, 256>>>();
    k_scanC<<<NB_SCAN, 256>>>();
    k_escatter<<<(EE + 255)/256, 256>>>(adj, et);
    k_fold_qa<<<64, 256>>>(qw, att);
    k_fold_ma<<<64, 256>>>(msg, aw);

    int nb = (NN + 127) / 128;
    k_kv<<<nb, 256, SM_KV>>>(h, kw, vw, nt);
    dim3 gq(nb, 4);
    k_qrel<<<gq, 256, SM_QREL>>>(h, nt);
    k_edge<<<(NN + 7)/8, 256>>>(pri);
    k_out<<<nb, 256, SM_OUT>>>(out, skip, nt);
}

// round 5
// speedup vs baseline: 1.2324x; 1.2324x over previous
#include <cuda_runtime.h>
#include <cuda_bf16.h>
#include <stdint.h>

#define NN 50000
#define EE 800000
#define TT 8
#define NB_SCAN 196

__device__ int   g_is64_adj, g_is64_et, g_is64_nt;
__device__ float g_knode[(size_t)NN*64];
__device__ float g_vnode[(size_t)NN*64];
__device__ __nv_bfloat16 g_qnH[(size_t)NN*64], g_qnL[(size_t)NN*64];
__device__ __nv_bfloat16 g_attH[512*64], g_attL[512*64];
__device__ __nv_bfloat16 g_msgTH[64*512], g_msgTL[64*512];
__device__ float g_qrel[(size_t)NN*512];
__device__ __nv_bfloat16 g_bkH[(size_t)NN*512], g_bkL[(size_t)NN*512];
__device__ float g_aggM[(size_t)NN*64];
__device__ int g_perm[NN], g_iperm[NN], g_deg[NN], g_cursor[NN], g_rowptr[NN+1];
__device__ int g_bsum[256], g_boff[256], g_tcount[TT], g_tbase[TT], g_tcur[TT];
__device__ int g_csr[EE];

__device__ __forceinline__ int ld_idx(const void* p, long i, int is64) {
    if (is64) return (int)(((const long long*)p)[i]);
    return ((const int*)p)[i];
}
// portable tensor-core mma (compiles for compute_103; lowers to HMMA)
__device__ __forceinline__ void mma_bf16(float* d, const uint32_t* a, uint32_t b0, uint32_t b1) {
    asm volatile("mma.sync.aligned.m16n8k16.row.col.f32.bf16.bf16.f32 "
        "{%0,%1,%2,%3},{%4,%5,%6,%7},{%8,%9},{%0,%1,%2,%3};"
        : "+f"(d[0]), "+f"(d[1]), "+f"(d[2]), "+f"(d[3])
        : "r"(a[0]), "r"(a[1]), "r"(a[2]), "r"(a[3]), "r"(b0), "r"(b1));
}

// ---------- plumbing ----------
__global__ void k_detect(const void* adj, const void* et, const void* nt) {
    if (threadIdx.x | blockIdx.x) return;
    int a=1,b=1,c=1;
    for (int i=0;i<128;i++) if (((const int*)adj)[2*(i*1000)+1]) { a=0; break; }
    for (int i=0;i<128;i++) if (((const int*)et )[2*(i*3000)+1]) { b=0; break; }
    for (int i=0;i<128;i++) if (((const int*)nt )[2*(i*150 )+1]) { c=0; break; }
    g_is64_adj=a; g_is64_et=b; g_is64_nt=c;
}
__global__ void k_zero() {
    int i = blockIdx.x*blockDim.x + threadIdx.x;
    if (i < NN) { g_deg[i]=0; g_cursor[i]=0; }
    if (i < TT) { g_tcount[i]=0; g_tcur[i]=0; }
    if (i == 0) g_rowptr[NN] = EE;
}
__global__ void k_nhist(const void* nt) {
    int i = blockIdx.x*blockDim.x + threadIdx.x;
    if (i < NN) atomicAdd(&g_tcount[ld_idx(nt,i,g_is64_nt)], 1);
}
__global__ void k_tscan() {
    if (threadIdx.x==0 && blockIdx.x==0) { int s=0; for (int t=0;t<TT;t++){ g_tbase[t]=s; s+=g_tcount[t]; } }
}
__global__ void k_nscatter(const void* nt) {
    int i = blockIdx.x*blockDim.x + threadIdx.x;
    if (i >= NN) return;
    int t = ld_idx(nt,i,g_is64_nt);
    g_perm[g_tbase[t] + atomicAdd(&g_tcur[t],1)] = i;
}
__global__ void k_iperm() {
    int i = blockIdx.x*blockDim.x + threadIdx.x;
    if (i < NN) g_iperm[g_perm[i]] = i;
}
__global__ void k_ehist(const void* adj) {
    int e = blockIdx.x*blockDim.x + threadIdx.x;
    if (e < EE) atomicAdd(&g_deg[g_iperm[ld_idx(adj,(long)EE+e,g_is64_adj)]], 1);
}
__global__ void k_scanA() {
    __shared__ int s[256];
    int i = blockIdx.x*256 + threadIdx.x;
    int v = (i < NN) ? g_deg[i] : 0;
    s[threadIdx.x] = v; __syncthreads();
    for (int off=1; off<256; off<<=1) {
        int t = (threadIdx.x>=off) ? s[threadIdx.x-off] : 0;
        __syncthreads(); s[threadIdx.x] += t; __syncthreads();
    }
    if (i < NN) g_rowptr[i] = s[threadIdx.x] - v;
    if (threadIdx.x == 255) g_bsum[blockIdx.x] = s[255];
}
__global__ void k_scanB() {
    __shared__ int s[256];
    int i = threadIdx.x;
    int v = (i < NB_SCAN) ? g_bsum[i] : 0;
    s[i] = v; __syncthreads();
    for (int off=1; off<256; off<<=1) {
        int t = (i>=off) ? s[i-off] : 0;
        __syncthreads(); s[i] += t; __syncthreads();
    }
    g_boff[i] = s[i] - v;
}
__global__ void k_scanC() {
    int i = blockIdx.x*256 + threadIdx.x;
    if (i < NN) g_rowptr[i] += g_boff[blockIdx.x];
}
__global__ void k_escatter(const void* adj, const void* et) {
    int e = blockIdx.x*blockDim.x + threadIdx.x;
    if (e >= EE) return;
    int src = ld_idx(adj, e, g_is64_adj);
    int dst = ld_idx(adj, (long)EE+e, g_is64_adj);
    int r   = ld_idx(et, e, g_is64_et);
    int dp = g_iperm[dst];
    g_csr[g_rowptr[dp] + atomicAdd(&g_cursor[dp],1)] = g_iperm[src] | (r << 20);
}
// ---------- bf16 hi/lo of att / msg^T ----------
__global__ void k_cvt(const float* __restrict__ att, const float* __restrict__ msg) {
    int i = blockIdx.x*256 + threadIdx.x;
    if (i >= 32768) return;
    float a = att[i];
    __nv_bfloat16 ah = __float2bfloat16_rn(a);
    g_attH[i] = ah; g_attL[i] = __float2bfloat16_rn(a - __bfloat162float(ah));
    float m = msg[i];
    int k = i >> 6, j = i & 63;
    __nv_bfloat16 mh = __float2bfloat16_rn(m);
    g_msgTH[j*512 + k] = mh;
    g_msgTL[j*512 + k] = __float2bfloat16_rn(m - __bfloat162float(mh));
}
// ---------- typed GEMM: knode, vnode, qnode(hi/lo bf16) ----------
__global__ __launch_bounds__(256,1) void k_kvq(const float* __restrict__ h, const float* __restrict__ kw,
                     const float* __restrict__ vw, const float* __restrict__ qw, const void* nt) {
    extern __shared__ float sm[];
    float* sA = sm;
    float* sWk = sA + 8192;
    float* sWv = sWk + 4096;
    float* sWq = sWv + 4096;
    int* sNode = (int*)(sWq + 4096);
    int* sTy = sNode + 128;
    int tid = threadIdx.x, base = blockIdx.x*128;
    if (tid < 128) {
        int idx = base + tid; if (idx > NN-1) idx = NN-1;
        int node = g_perm[idx];
        sNode[tid] = node;
        sTy[tid] = ld_idx(nt, node, g_is64_nt);
    }
    __syncthreads();
    {
        int m = tid >> 1, half = tid & 1;
        const float4* hp = (const float4*)(h + (size_t)sNode[m]*64 + half*32);
        #pragma unroll
        for (int j = 0; j < 8; j++) {
            float4 v = hp[j]; int k0 = half*32 + j*4;
            sA[(k0+0)*128+m]=v.x; sA[(k0+1)*128+m]=v.y; sA[(k0+2)*128+m]=v.z; sA[(k0+3)*128+m]=v.w;
        }
    }
    __syncthreads();
    int t0 = sTy[0], t1 = sTy[127];
    int wy = tid >> 4, wx = tid & 15;
    int m0 = wy*8, c0 = wx*4;
    for (int t = t0; t <= t1; t++) {
        for (int e = tid; e < 1024; e += 256) {
            ((float4*)sWk)[e] = ((const float4*)(kw + t*4096))[e];
            ((float4*)sWv)[e] = ((const float4*)(vw + t*4096))[e];
            ((float4*)sWq)[e] = ((const float4*)(qw + t*4096))[e];
        }
        __syncthreads();
        float aK[8][4], aV[8][4], aQ[8][4];
        #pragma unroll
        for (int i = 0; i < 8; i++)
            #pragma unroll
            for (int j = 0; j < 4; j++) { aK[i][j]=0.f; aV[i][j]=0.f; aQ[i][j]=0.f; }
        #pragma unroll 2
        for (int k = 0; k < 64; k++) {
            float4 bk = *(const float4*)&sWk[k*64+c0];
            float4 bv = *(const float4*)&sWv[k*64+c0];
            float4 bq = *(const float4*)&sWq[k*64+c0];
            float4 a0 = *(const float4*)&sA[k*128+m0];
            float4 a1 = *(const float4*)&sA[k*128+m0+4];
            float av[8] = {a0.x,a0.y,a0.z,a0.w,a1.x,a1.y,a1.z,a1.w};
            #pragma unroll
            for (int i = 0; i < 8; i++) {
                aK[i][0]+=av[i]*bk.x; aK[i][1]+=av[i]*bk.y; aK[i][2]+=av[i]*bk.z; aK[i][3]+=av[i]*bk.w;
                aV[i][0]+=av[i]*bv.x; aV[i][1]+=av[i]*bv.y; aV[i][2]+=av[i]*bv.z; aV[i][3]+=av[i]*bv.w;
                aQ[i][0]+=av[i]*bq.x; aQ[i][1]+=av[i]*bq.y; aQ[i][2]+=av[i]*bq.z; aQ[i][3]+=av[i]*bq.w;
            }
        }
        #pragma unroll
        for (int i = 0; i < 8; i++) {
            int row = m0 + i, idx = base + row;
            if (idx < NN && sTy[row] == t) {
                *(float4*)&g_knode[(size_t)idx*64+c0] = make_float4(aK[i][0],aK[i][1],aK[i][2],aK[i][3]);
                *(float4*)&g_vnode[(size_t)idx*64+c0] = make_float4(aV[i][0],aV[i][1],aV[i][2],aV[i][3]);
                __nv_bfloat162 h0, h1, l0, l1;
                h0.x=__float2bfloat16_rn(aQ[i][0]); h0.y=__float2bfloat16_rn(aQ[i][1]);
                h1.x=__float2bfloat16_rn(aQ[i][2]); h1.y=__float2bfloat16_rn(aQ[i][3]);
                l0.x=__float2bfloat16_rn(aQ[i][0]-__bfloat162float(h0.x));
                l0.y=__float2bfloat16_rn(aQ[i][1]-__bfloat162float(h0.y));
                l1.x=__float2bfloat16_rn(aQ[i][2]-__bfloat162float(h1.x));
                l1.y=__float2bfloat16_rn(aQ[i][3]-__bfloat162float(h1.y));
                size_t o = (size_t)idx*64 + c0;
                *(__nv_bfloat162*)&g_qnH[o]=h0; *(__nv_bfloat162*)&g_qnH[o+2]=h1;
                *(__nv_bfloat162*)&g_qnL[o]=l0; *(__nv_bfloat162*)&g_qnL[o+2]=l1;
            }
        }
        __syncthreads();
    }
}
// ---------- mma GEMM 1: qrel[128,512] = qn[128,64] @ att^T (3-term bf16 split) ----------
// smem stride 72 bf16 (144B) -> conflict-free quad access
__global__ __launch_bounds__(256,1) void mma_qrel() {
    extern __shared__ __nv_bfloat16 sb[];
    __nv_bfloat16 *sAH = sb, *sAL = sb+9216, *sBH = sb+18432, *sBL = sb+27648;
    int tid = threadIdx.x, lane = tid & 31, w = tid >> 5;
    int base = blockIdx.x*128;
    for (int u = tid; u < 1024; u += 256) {
        int row = u>>3, q = u&7;
        int idx = base+row; if (idx > NN-1) idx = NN-1;
        *(uint4*)(sAH + row*72 + q*8) = *(const uint4*)(g_qnH + (size_t)idx*64 + q*8);
        *(uint4*)(sAL + row*72 + q*8) = *(const uint4*)(g_qnL + (size_t)idx*64 + q*8);
    }
    __syncthreads();
    int m0 = w*16, r = lane>>2, cq = (lane&3)*2;
    uint32_t AH[4][4], AL[4][4];
    #pragma unroll
    for (int ks = 0; ks < 4; ks++) {
        int c = ks*16 + cq;
        AH[ks][0] = *(const uint32_t*)(sAH + (m0+r  )*72 + c);
        AH[ks][1] = *(const uint32_t*)(sAH + (m0+r+8)*72 + c);
        AH[ks][2] = *(const uint32_t*)(sAH + (m0+r  )*72 + c + 8);
        AH[ks][3] = *(const uint32_t*)(sAH + (m0+r+8)*72 + c + 8);
        AL[ks][0] = *(const uint32_t*)(sAL + (m0+r  )*72 + c);
        AL[ks][1] = *(const uint32_t*)(sAL + (m0+r+8)*72 + c);
        AL[ks][2] = *(const uint32_t*)(sAL + (m0+r  )*72 + c + 8);
        AL[ks][3] = *(const uint32_t*)(sAL + (m0+r+8)*72 + c + 8);
    }
    int gr0 = base + m0 + r, gr1 = gr0 + 8;
    for (int nc = 0; nc < 4; nc++) {
        if (nc) __syncthreads();
        for (int u = tid; u < 1024; u += 256) {
            int row = u>>3, q = u&7;
            *(uint4*)(sBH + row*72 + q*8) = *(const uint4*)(g_attH + (size_t)(nc*128+row)*64 + q*8);
            *(uint4*)(sBL + row*72 + q*8) = *(const uint4*)(g_attL + (size_t)(nc*128+row)*64 + q*8);
        }
        __syncthreads();
        #pragma unroll 4
        for (int nt = 0; nt < 16; nt++) {
            float acc[4] = {0.f, 0.f, 0.f, 0.f};
            int brow = nt*8 + r;
            #pragma unroll
            for (int ks = 0; ks < 4; ks++) {
                int bc = ks*16 + cq;
                uint32_t bh0 = *(const uint32_t*)(sBH + brow*72 + bc);
                uint32_t bh1 = *(const uint32_t*)(sBH + brow*72 + bc + 8);
                uint32_t bl0 = *(const uint32_t*)(sBL + brow*72 + bc);
                uint32_t bl1 = *(const uint32_t*)(sBL + brow*72 + bc + 8);
                mma_bf16(acc, AH[ks], bh0, bh1);
                mma_bf16(acc, AL[ks], bh0, bh1);
                mma_bf16(acc, AH[ks], bl0, bl1);
            }
            int gc = nc*128 + nt*8 + cq;
            if (gr0 < NN) *(float2*)&g_qrel[(size_t)gr0*512 + gc] = make_float2(acc[0], acc[1]);
            if (gr1 < NN) *(float2*)&g_qrel[(size_t)gr1*512 + gc] = make_float2(acc[2], acc[3]);
        }
    }
}
// ---------- fused edge phase ----------
__global__ void k_edge(const float* __restrict__ pri) {
    int d = blockIdx.x*8 + (threadIdx.x>>5);
    if (d >= NN) return;
    int lane = threadIdx.x & 31;
    float2 q[8]; float pr[8];
    #pragma unroll
    for (int r = 0; r < 8; r++) {
        q[r] = *(const float2*)&g_qrel[(size_t)d*512 + r*64 + lane*2];
        pr[r] = pri[r] * 0.125f;
    }
    int rs = g_rowptr[d], re = g_rowptr[d+1];
    float m = -3.0e38f, s = 0.f;
    float2 b[8];
    #pragma unroll
    for (int r = 0; r < 8; r++) b[r] = make_float2(0.f,0.f);
    for (int p = rs; p < re; p++) {
        int pk = g_csr[p], sp = pk & 0xFFFFF, r = pk >> 20;
        float2 kv = *(const float2*)&g_knode[(size_t)sp*64 + lane*2];
        float2 qs = q[0]; float prs = pr[0];
        #pragma unroll
        for (int rr = 1; rr < 8; rr++) if (r == rr) { qs = q[rr]; prs = pr[rr]; }
        float part = kv.x*qs.x + kv.y*qs.y;
        part += __shfl_xor_sync(~0u, part, 16);
        part += __shfl_xor_sync(~0u, part, 8);
        part += __shfl_xor_sync(~0u, part, 4);
        part += __shfl_xor_sync(~0u, part, 2);
        part += __shfl_xor_sync(~0u, part, 1);
        float score = part * prs;
        float2 vv = *(const float2*)&g_vnode[(size_t)sp*64 + lane*2];
        if (score > m) {
            float c = __expf(m - score);
            s *= c;
            #pragma unroll
            for (int rr = 0; rr < 8; rr++) { b[rr].x *= c; b[rr].y *= c; }
            m = score;
        }
        float w = __expf(score - m);
        s += w;
        #pragma unroll
        for (int rr = 0; rr < 8; rr++) if (r == rr) { b[rr].x += w*vv.x; b[rr].y += w*vv.y; }
    }
    float inv = 1.0f / (s + 1e-16f);
    #pragma unroll
    for (int r = 0; r < 8; r++) {
        float ox = b[r].x*inv, oy = b[r].y*inv;
        __nv_bfloat162 h2, l2;
        h2.x = __float2bfloat16_rn(ox); h2.y = __float2bfloat16_rn(oy);
        l2.x = __float2bfloat16_rn(ox - __bfloat162float(h2.x));
        l2.y = __float2bfloat16_rn(oy - __bfloat162float(h2.y));
        size_t o = (size_t)d*512 + r*64 + lane*2;
        *(__nv_bfloat162*)&g_bkH[o] = h2;
        *(__nv_bfloat162*)&g_bkL[o] = l2;
    }
}
// ---------- mma GEMM 2: aggM[128,64] = bucket[128,512] @ Mstack (K staged 8x64) ----------
__global__ __launch_bounds__(256,1) void mma_agg() {
    extern __shared__ __nv_bfloat16 sb[];
    __nv_bfloat16 *sAH = sb, *sAL = sb+9216, *sBH = sb+18432, *sBL = sb+23040;
    int tid = threadIdx.x, lane = tid & 31, w = tid >> 5;
    int base = blockIdx.x*128;
    int m0 = w*16, r = lane>>2, cq = (lane&3)*2;
    float acc[8][4];
    #pragma unroll
    for (int nt = 0; nt < 8; nt++)
        #pragma unroll
        for (int j = 0; j < 4; j++) acc[nt][j] = 0.f;
    for (int kp = 0; kp < 8; kp++) {
        if (kp) __syncthreads();
        for (int u = tid; u < 1024; u += 256) {
            int row = u>>3, q = u&7;
            int idx = base+row; if (idx > NN-1) idx = NN-1;
            size_t g = (size_t)idx*512 + kp*64 + q*8;
            *(uint4*)(sAH + row*72 + q*8) = *(const uint4*)(g_bkH + g);
            *(uint4*)(sAL + row*72 + q*8) = *(const uint4*)(g_bkL + g);
        }
        for (int u = tid; u < 512; u += 256) {
            int row = u>>3, q = u&7;
            size_t g = (size_t)row*512 + kp*64 + q*8;
            *(uint4*)(sBH + row*72 + q*8) = *(const uint4*)(g_msgTH + g);
            *(uint4*)(sBL + row*72 + q*8) = *(const uint4*)(g_msgTL + g);
        }
        __syncthreads();
        uint32_t AH[4][4], AL[4][4];
        #pragma unroll
        for (int ks = 0; ks < 4; ks++) {
            int c = ks*16 + cq;
            AH[ks][0] = *(const uint32_t*)(sAH + (m0+r  )*72 + c);
            AH[ks][1] = *(const uint32_t*)(sAH + (m0+r+8)*72 + c);
            AH[ks][2] = *(const uint32_t*)(sAH + (m0+r  )*72 + c + 8);
            AH[ks][3] = *(const uint32_t*)(sAH + (m0+r+8)*72 + c + 8);
            AL[ks][0] = *(const uint32_t*)(sAL + (m0+r  )*72 + c);
            AL[ks][1] = *(const uint32_t*)(sAL + (m0+r+8)*72 + c);
            AL[ks][2] = *(const uint32_t*)(sAL + (m0+r  )*72 + c + 8);
            AL[ks][3] = *(const uint32_t*)(sAL + (m0+r+8)*72 + c + 8);
        }
        #pragma unroll
        for (int nt = 0; nt < 8; nt++) {
            int brow = nt*8 + r;
            #pragma unroll
            for (int ks = 0; ks < 4; ks++) {
                int bc = ks*16 + cq;
                uint32_t bh0 = *(const uint32_t*)(sBH + brow*72 + bc);
                uint32_t bh1 = *(const uint32_t*)(sBH + brow*72 + bc + 8);
                uint32_t bl0 = *(const uint32_t*)(sBL + brow*72 + bc);
                uint32_t bl1 = *(const uint32_t*)(sBL + brow*72 + bc + 8);
                mma_bf16(acc[nt], AH[ks], bh0, bh1);
                mma_bf16(acc[nt], AL[ks], bh0, bh1);
                mma_bf16(acc[nt], AH[ks], bl0, bl1);
            }
        }
    }
    int gr0 = base + m0 + r, gr1 = gr0 + 8;
    #pragma unroll
    for (int nt = 0; nt < 8; nt++) {
        int gc = nt*8 + cq;
        if (gr0 < NN) *(float2*)&g_aggM[(size_t)gr0*64 + gc] = make_float2(acc[nt][0], acc[nt][1]);
        if (gr1 < NN) *(float2*)&g_aggM[(size_t)gr1*64 + gc] = make_float2(acc[nt][2], acc[nt][3]);
    }
}
// ---------- typed final GEMM: out = aggM @ aw[t] * sigmoid(skip[t]) ----------
__global__ __launch_bounds__(256,1) void k_outT(float* __restrict__ out, const float* __restrict__ aw,
                      const float* __restrict__ skipv, const void* nt) {
    extern __shared__ float sm[];
    float* sA = sm;
    float* sW = sA + 8192;
    int* sNode = (int*)(sW + 4096);
    int* sTy = sNode + 128;
    int tid = threadIdx.x, base = blockIdx.x*128;
    if (tid < 128) {
        int idx = base + tid; if (idx > NN-1) idx = NN-1;
        int node = g_perm[idx];
        sNode[tid] = node;
        sTy[tid] = ld_idx(nt, node, g_is64_nt);
    }
    __syncthreads();
    {
        int m = tid >> 1, half = tid & 1;
        int idx = base + m; if (idx > NN-1) idx = NN-1;
        const float4* hp = (const float4*)(g_aggM + (size_t)idx*64 + half*32);
        #pragma unroll
        for (int j = 0; j < 8; j++) {
            float4 v = hp[j]; int k0 = half*32 + j*4;
            sA[(k0+0)*128+m]=v.x; sA[(k0+1)*128+m]=v.y; sA[(k0+2)*128+m]=v.z; sA[(k0+3)*128+m]=v.w;
        }
    }
    __syncthreads();
    int t0 = sTy[0], t1 = sTy[127];
    int wy = tid >> 4, wx = tid & 15;
    int m0 = wy*8, c0 = wx*4;
    for (int t = t0; t <= t1; t++) {
        for (int e = tid; e < 1024; e += 256)
            ((float4*)sW)[e] = ((const float4*)(aw + t*4096))[e];
        __syncthreads();
        float acc[8][4];
        #pragma unroll
        for (int i = 0; i < 8; i++)
            #pragma unroll
            for (int j = 0; j < 4; j++) acc[i][j] = 0.f;
        #pragma unroll 4
        for (int k = 0; k < 64; k++) {
            float4 bw = *(const float4*)&sW[k*64+c0];
            float4 a0 = *(const float4*)&sA[k*128+m0];
            float4 a1 = *(const float4*)&sA[k*128+m0+4];
            float av[8] = {a0.x,a0.y,a0.z,a0.w,a1.x,a1.y,a1.z,a1.w};
            #pragma unroll
            for (int i = 0; i < 8; i++) {
                acc[i][0]+=av[i]*bw.x; acc[i][1]+=av[i]*bw.y; acc[i][2]+=av[i]*bw.z; acc[i][3]+=av[i]*bw.w;
            }
        }
        float sc = 1.0f / (1.0f + __expf(-skipv[t]));
        #pragma unroll
        for (int i = 0; i < 8; i++) {
            int row = m0 + i, idx = base + row;
            if (idx < NN && sTy[row] == t)
                *(float4*)&out[(size_t)sNode[row]*64+c0] =
                    make_float4(acc[i][0]*sc, acc[i][1]*sc, acc[i][2]*sc, acc[i][3]*sc);
        }
        __syncthreads();
    }
}

extern "C" void kernel_launch(void* const* d_in, const int* in_sizes, int n_in,
                              void* d_out, int out_size) {
    const float* h   = (const float*)d_in[0];
    const void*  adj = d_in[1];
    const void*  et  = d_in[2];
    const void*  nt  = d_in[3];
    int off = n_in - 8;
    const float* kw   = (const float*)d_in[off+0];
    const float* qw   = (const float*)d_in[off+1];
    const float* vw   = (const float*)d_in[off+2];
    const float* aw   = (const float*)d_in[off+3];
    const float* pri  = (const float*)d_in[off+4];
    const float* msg  = (const float*)d_in[off+6];
    const float* att  = (const float*)d_in[off+5];
    const float* skip = (const float*)d_in[off+7];
    float* out = (float*)d_out;

    const int SM_KVQ  = (8192 + 3*4096)*4 + 256*4 + 16;
    const int SM_QREL = 4*9216*2;             // 73728 B
    const int SM_AGG  = (2*9216 + 2*4608)*2;  // 55296 B
    const int SM_OUT  = (8192 + 4096)*4 + 256*4 + 16;
    cudaFuncSetAttribute(k_kvq,    cudaFuncAttributeMaxDynamicSharedMemorySize, SM_KVQ);
    cudaFuncSetAttribute(mma_qrel, cudaFuncAttributeMaxDynamicSharedMemorySize, SM_QREL);
    cudaFuncSetAttribute(mma_agg,  cudaFuncAttributeMaxDynamicSharedMemorySize, SM_AGG);
    cudaFuncSetAttribute(k_outT,   cudaFuncAttributeMaxDynamicSharedMemorySize, SM_OUT);

    k_detect<<<1,1>>>(adj, et, nt);
    k_zero<<<(NN+255)/256,256>>>();
    k_nhist<<<(NN+255)/256,256>>>(nt);
    k_tscan<<<1,1>>>();
    k_nscatter<<<(NN+255)/256,256>>>(nt);
    k_iperm<<<(NN+255)/256,256>>>();
    k_ehist<<<(EE+255)/256,256>>>(adj);
    k_scanA<<<NB_SCAN,256>>>();
    k_scanB<<<1,256>>>();
    k_scanC<<<NB_SCAN,256>>>();
    k_escatter<<<(EE+255)/256,256>>>(adj, et);
    k_cvt<<<128,256>>>(att, msg);

    int nb = (NN + 127) / 128;
    k_kvq<<<nb,256,SM_KVQ>>>(h, kw, vw, qw, nt);
    mma_qrel<<<nb,256,SM_QREL>>>();
    k_edge<<<(NN+7)/8,256>>>(pri);
    mma_agg<<<nb,256,SM_AGG>>>();
    k_outT<<<nb,256,SM_OUT>>>(out, aw, skip, nt);
}

// round 6
// speedup vs baseline: 1.5149x; 1.2292x over previous
#include <cuda_runtime.h>
#include <cuda_bf16.h>
#include <stdint.h>

#define NN 50000
#define EE 800000
#define TT 8
#define NB_SCAN 196

__device__ int   g_is64_adj, g_is64_et, g_is64_nt;
__device__ float g_knode[(size_t)NN*64];
__device__ float g_vnode[(size_t)NN*64];
__device__ __nv_bfloat16 g_hH[(size_t)NN*64], g_hL[(size_t)NN*64];
__device__ __nv_bfloat16 g_qnH[(size_t)NN*64], g_qnL[(size_t)NN*64];
__device__ __nv_bfloat16 g_wTH[3*TT*4096], g_wTL[3*TT*4096];   // k,v,q transposed [mat][t][c][k]
__device__ __nv_bfloat16 g_attH[512*64], g_attL[512*64];
__device__ __nv_bfloat16 g_msgTH[64*512], g_msgTL[64*512];
__device__ float g_qrel[(size_t)NN*512];
__device__ __nv_bfloat16 g_bkH[(size_t)NN*512], g_bkL[(size_t)NN*512];
__device__ float g_aggM[(size_t)NN*64];
__device__ int g_perm[NN], g_iperm[NN], g_deg[NN], g_cursor[NN], g_rowptr[NN+1];
__device__ int g_bsum[256], g_boff[256], g_tcount[TT], g_tbase[TT], g_tcur[TT];
__device__ int g_csr[EE];

__device__ __forceinline__ int ld_idx(const void* p, long i, int is64) {
    if (is64) return (int)(((const long long*)p)[i]);
    return ((const int*)p)[i];
}
__device__ __forceinline__ void mma_bf16(float* d, const uint32_t* a, uint32_t b0, uint32_t b1) {
    asm volatile("mma.sync.aligned.m16n8k16.row.col.f32.bf16.bf16.f32 "
        "{%0,%1,%2,%3},{%4,%5,%6,%7},{%8,%9},{%0,%1,%2,%3};"
        : "+f"(d[0]), "+f"(d[1]), "+f"(d[2]), "+f"(d[3])
        : "r"(a[0]), "r"(a[1]), "r"(a[2]), "r"(a[3]), "r"(b0), "r"(b1));
}

// ---------- plumbing ----------
__global__ void k_detect(const void* adj, const void* et, const void* nt) {
    if (threadIdx.x | blockIdx.x) return;
    int a=1,b=1,c=1;
    for (int i=0;i<128;i++) if (((const int*)adj)[2*(i*1000)+1]) { a=0; break; }
    for (int i=0;i<128;i++) if (((const int*)et )[2*(i*3000)+1]) { b=0; break; }
    for (int i=0;i<128;i++) if (((const int*)nt )[2*(i*150 )+1]) { c=0; break; }
    g_is64_adj=a; g_is64_et=b; g_is64_nt=c;
}
__global__ void k_zero() {
    int i = blockIdx.x*blockDim.x + threadIdx.x;
    if (i < NN) { g_deg[i]=0; g_cursor[i]=0; }
    if (i < TT) { g_tcount[i]=0; g_tcur[i]=0; }
    if (i == 0) g_rowptr[NN] = EE;
}
__global__ void k_nhist(const void* nt) {
    int i = blockIdx.x*blockDim.x + threadIdx.x;
    if (i < NN) atomicAdd(&g_tcount[ld_idx(nt,i,g_is64_nt)], 1);
}
__global__ void k_tscan() {
    if (threadIdx.x==0 && blockIdx.x==0) { int s=0; for (int t=0;t<TT;t++){ g_tbase[t]=s; s+=g_tcount[t]; } }
}
__global__ void k_nscatter(const void* nt) {
    int i = blockIdx.x*blockDim.x + threadIdx.x;
    if (i >= NN) return;
    int t = ld_idx(nt,i,g_is64_nt);
    g_perm[g_tbase[t] + atomicAdd(&g_tcur[t],1)] = i;
}
__global__ void k_iperm() {
    int i = blockIdx.x*blockDim.x + threadIdx.x;
    if (i < NN) g_iperm[g_perm[i]] = i;
}
__global__ void k_ehist(const void* adj) {
    int e = blockIdx.x*blockDim.x + threadIdx.x;
    if (e < EE) atomicAdd(&g_deg[g_iperm[ld_idx(adj,(long)EE+e,g_is64_adj)]], 1);
}
__global__ void k_scanA() {
    __shared__ int s[256];
    int i = blockIdx.x*256 + threadIdx.x;
    int v = (i < NN) ? g_deg[i] : 0;
    s[threadIdx.x] = v; __syncthreads();
    for (int off=1; off<256; off<<=1) {
        int t = (threadIdx.x>=off) ? s[threadIdx.x-off] : 0;
        __syncthreads(); s[threadIdx.x] += t; __syncthreads();
    }
    if (i < NN) g_rowptr[i] = s[threadIdx.x] - v;
    if (threadIdx.x == 255) g_bsum[blockIdx.x] = s[255];
}
__global__ void k_scanB() {
    __shared__ int s[256];
    int i = threadIdx.x;
    int v = (i < NB_SCAN) ? g_bsum[i] : 0;
    s[i] = v; __syncthreads();
    for (int off=1; off<256; off<<=1) {
        int t = (i>=off) ? s[i-off] : 0;
        __syncthreads(); s[i] += t; __syncthreads();
    }
    g_boff[i] = s[i] - v;
}
__global__ void k_scanC() {
    int i = blockIdx.x*256 + threadIdx.x;
    if (i < NN) g_rowptr[i] += g_boff[blockIdx.x];
}
__global__ void k_escatter(const void* adj, const void* et) {
    int e = blockIdx.x*blockDim.x + threadIdx.x;
    if (e >= EE) return;
    int src = ld_idx(adj, e, g_is64_adj);
    int dst = ld_idx(adj, (long)EE+e, g_is64_adj);
    int r   = ld_idx(et, e, g_is64_et);
    int dp = g_iperm[dst];
    g_csr[g_rowptr[dp] + atomicAdd(&g_cursor[dp],1)] = g_iperm[src] | (r << 20);
}
// ---------- bf16 hi/lo conversions ----------
__global__ void k_cvt(const float* __restrict__ att, const float* __restrict__ msg) {
    int i = blockIdx.x*256 + threadIdx.x;
    if (i >= 32768) return;
    float a = att[i];
    __nv_bfloat16 ah = __float2bfloat16_rn(a);
    g_attH[i] = ah; g_attL[i] = __float2bfloat16_rn(a - __bfloat162float(ah));
    float m = msg[i];
    int k = i >> 6, j = i & 63;
    __nv_bfloat16 mh = __float2bfloat16_rn(m);
    g_msgTH[j*512 + k] = mh;
    g_msgTL[j*512 + k] = __float2bfloat16_rn(m - __bfloat162float(mh));
}
__global__ void k_cvtw(const float* __restrict__ kw, const float* __restrict__ vw, const float* __restrict__ qw) {
    int i = blockIdx.x*256 + threadIdx.x;
    if (i >= 3*TT*4096) return;
    int mat = i >> 15, rem = i & 32767;
    int t = rem >> 12, e = rem & 4095;
    int k = e >> 6, c = e & 63;
    const float* W = (mat == 0) ? kw : (mat == 1) ? vw : qw;
    float v = W[t*4096 + k*64 + c];
    __nv_bfloat16 vh = __float2bfloat16_rn(v);
    int o = i - e + c*64 + k;   // transposed within [t] block
    g_wTH[o] = vh; g_wTL[o] = __float2bfloat16_rn(v - __bfloat162float(vh));
}
__global__ void k_cvth(const float* __restrict__ h) {
    int i = blockIdx.x*256 + threadIdx.x;
    if (i >= NN*64) return;
    float v = h[i];
    __nv_bfloat16 vh = __float2bfloat16_rn(v);
    g_hH[i] = vh; g_hL[i] = __float2bfloat16_rn(v - __bfloat162float(vh));
}
// ---------- mma typed GEMM: knode/vnode fp32 + qn hi/lo ----------
__global__ __launch_bounds__(256,1) void mma_kvq(const void* nt) {
    extern __shared__ __nv_bfloat16 sb[];
    __nv_bfloat16 *sAH = sb, *sAL = sb+9216;          // 128x72 each
    __nv_bfloat16 *sBH = sb+18432, *sBL = sb+18432+13824; // 3 panels of 64x72 each
    int* sNode = (int*)(sb + 46080);
    int* sTy = sNode + 128;
    int tid = threadIdx.x, lane = tid & 31, w = tid >> 5;
    int base = blockIdx.x*128;
    if (tid < 128) {
        int idx = base + tid; if (idx > NN-1) idx = NN-1;
        int node = g_perm[idx];
        sNode[tid] = node;
        sTy[tid] = ld_idx(nt, node, g_is64_nt);
    }
    __syncthreads();
    for (int u = tid; u < 1024; u += 256) {
        int row = u>>3, q = u&7;
        size_t g = (size_t)sNode[row]*64 + q*8;
        *(uint4*)(sAH + row*72 + q*8) = *(const uint4*)(g_hH + g);
        *(uint4*)(sAL + row*72 + q*8) = *(const uint4*)(g_hL + g);
    }
    __syncthreads();
    int m0 = w*16, r = lane>>2, cq = (lane&3)*2;
    uint32_t AH[4][4], AL[4][4];
    #pragma unroll
    for (int ks = 0; ks < 4; ks++) {
        int c = ks*16 + cq;
        AH[ks][0] = *(const uint32_t*)(sAH + (m0+r  )*72 + c);
        AH[ks][1] = *(const uint32_t*)(sAH + (m0+r+8)*72 + c);
        AH[ks][2] = *(const uint32_t*)(sAH + (m0+r  )*72 + c + 8);
        AH[ks][3] = *(const uint32_t*)(sAH + (m0+r+8)*72 + c + 8);
        AL[ks][0] = *(const uint32_t*)(sAL + (m0+r  )*72 + c);
        AL[ks][1] = *(const uint32_t*)(sAL + (m0+r+8)*72 + c);
        AL[ks][2] = *(const uint32_t*)(sAL + (m0+r  )*72 + c + 8);
        AL[ks][3] = *(const uint32_t*)(sAL + (m0+r+8)*72 + c + 8);
    }
    int t0 = sTy[0], t1 = sTy[127];
    int gr0 = base + m0 + r, gr1 = gr0 + 8;
    int row0 = m0 + r, row1 = row0 + 8;
    for (int t = t0; t <= t1; t++) {
        if (t > t0) __syncthreads();
        for (int u = tid; u < 1536; u += 256) {
            int mat = u >> 9, e = u & 511;
            int row = e>>3, q = e&7;
            size_t g = (size_t)(mat*TT + t)*4096 + row*64 + q*8;
            *(uint4*)(sBH + mat*4608 + row*72 + q*8) = *(const uint4*)(g_wTH + g);
            *(uint4*)(sBL + mat*4608 + row*72 + q*8) = *(const uint4*)(g_wTL + g);
        }
        __syncthreads();
        bool ok0 = (gr0 < NN) && (sTy[row0] == t);
        bool ok1 = (gr1 < NN) && (sTy[row1] == t);
        #pragma unroll
        for (int mat = 0; mat < 3; mat++) {
            const __nv_bfloat16 *BH = sBH + mat*4608, *BL = sBL + mat*4608;
            #pragma unroll
            for (int ntl = 0; ntl < 8; ntl++) {
                float acc[4] = {0.f,0.f,0.f,0.f};
                int brow = ntl*8 + r;
                #pragma unroll
                for (int ks = 0; ks < 4; ks++) {
                    int bc = ks*16 + cq;
                    uint32_t bh0 = *(const uint32_t*)(BH + brow*72 + bc);
                    uint32_t bh1 = *(const uint32_t*)(BH + brow*72 + bc + 8);
                    uint32_t bl0 = *(const uint32_t*)(BL + brow*72 + bc);
                    uint32_t bl1 = *(const uint32_t*)(BL + brow*72 + bc + 8);
                    mma_bf16(acc, AH[ks], bh0, bh1);
                    mma_bf16(acc, AL[ks], bh0, bh1);
                    mma_bf16(acc, AH[ks], bl0, bl1);
                }
                int gc = ntl*8 + cq;
                if (mat == 0) {
                    if (ok0) *(float2*)&g_knode[(size_t)gr0*64+gc] = make_float2(acc[0],acc[1]);
                    if (ok1) *(float2*)&g_knode[(size_t)gr1*64+gc] = make_float2(acc[2],acc[3]);
                } else if (mat == 1) {
                    if (ok0) *(float2*)&g_vnode[(size_t)gr0*64+gc] = make_float2(acc[0],acc[1]);
                    if (ok1) *(float2*)&g_vnode[(size_t)gr1*64+gc] = make_float2(acc[2],acc[3]);
                } else {
                    if (ok0) {
                        __nv_bfloat162 h2,l2;
                        h2.x=__float2bfloat16_rn(acc[0]); h2.y=__float2bfloat16_rn(acc[1]);
                        l2.x=__float2bfloat16_rn(acc[0]-__bfloat162float(h2.x));
                        l2.y=__float2bfloat16_rn(acc[1]-__bfloat162float(h2.y));
                        size_t o = (size_t)gr0*64+gc;
                        *(__nv_bfloat162*)&g_qnH[o]=h2; *(__nv_bfloat162*)&g_qnL[o]=l2;
                    }
                    if (ok1) {
                        __nv_bfloat162 h2,l2;
                        h2.x=__float2bfloat16_rn(acc[2]); h2.y=__float2bfloat16_rn(acc[3]);
                        l2.x=__float2bfloat16_rn(acc[2]-__bfloat162float(h2.x));
                        l2.y=__float2bfloat16_rn(acc[3]-__bfloat162float(h2.y));
                        size_t o = (size_t)gr1*64+gc;
                        *(__nv_bfloat162*)&g_qnH[o]=h2; *(__nv_bfloat162*)&g_qnL[o]=l2;
                    }
                }
            }
        }
    }
}
// ---------- mma GEMM 1: qrel[128,512] = qn @ att^T ----------
__global__ __launch_bounds__(256,1) void mma_qrel() {
    extern __shared__ __nv_bfloat16 sb[];
    __nv_bfloat16 *sAH = sb, *sAL = sb+9216, *sBH = sb+18432, *sBL = sb+27648;
    int tid = threadIdx.x, lane = tid & 31, w = tid >> 5;
    int base = blockIdx.x*128;
    for (int u = tid; u < 1024; u += 256) {
        int row = u>>3, q = u&7;
        int idx = base+row; if (idx > NN-1) idx = NN-1;
        *(uint4*)(sAH + row*72 + q*8) = *(const uint4*)(g_qnH + (size_t)idx*64 + q*8);
        *(uint4*)(sAL + row*72 + q*8) = *(const uint4*)(g_qnL + (size_t)idx*64 + q*8);
    }
    __syncthreads();
    int m0 = w*16, r = lane>>2, cq = (lane&3)*2;
    uint32_t AH[4][4], AL[4][4];
    #pragma unroll
    for (int ks = 0; ks < 4; ks++) {
        int c = ks*16 + cq;
        AH[ks][0] = *(const uint32_t*)(sAH + (m0+r  )*72 + c);
        AH[ks][1] = *(const uint32_t*)(sAH + (m0+r+8)*72 + c);
        AH[ks][2] = *(const uint32_t*)(sAH + (m0+r  )*72 + c + 8);
        AH[ks][3] = *(const uint32_t*)(sAH + (m0+r+8)*72 + c + 8);
        AL[ks][0] = *(const uint32_t*)(sAL + (m0+r  )*72 + c);
        AL[ks][1] = *(const uint32_t*)(sAL + (m0+r+8)*72 + c);
        AL[ks][2] = *(const uint32_t*)(sAL + (m0+r  )*72 + c + 8);
        AL[ks][3] = *(const uint32_t*)(sAL + (m0+r+8)*72 + c + 8);
    }
    int gr0 = base + m0 + r, gr1 = gr0 + 8;
    for (int nc = 0; nc < 4; nc++) {
        if (nc) __syncthreads();
        for (int u = tid; u < 1024; u += 256) {
            int row = u>>3, q = u&7;
            *(uint4*)(sBH + row*72 + q*8) = *(const uint4*)(g_attH + (size_t)(nc*128+row)*64 + q*8);
            *(uint4*)(sBL + row*72 + q*8) = *(const uint4*)(g_attL + (size_t)(nc*128+row)*64 + q*8);
        }
        __syncthreads();
        #pragma unroll 4
        for (int ntl = 0; ntl < 16; ntl++) {
            float acc[4] = {0.f, 0.f, 0.f, 0.f};
            int brow = ntl*8 + r;
            #pragma unroll
            for (int ks = 0; ks < 4; ks++) {
                int bc = ks*16 + cq;
                uint32_t bh0 = *(const uint32_t*)(sBH + brow*72 + bc);
                uint32_t bh1 = *(const uint32_t*)(sBH + brow*72 + bc + 8);
                uint32_t bl0 = *(const uint32_t*)(sBL + brow*72 + bc);
                uint32_t bl1 = *(const uint32_t*)(sBL + brow*72 + bc + 8);
                mma_bf16(acc, AH[ks], bh0, bh1);
                mma_bf16(acc, AL[ks], bh0, bh1);
                mma_bf16(acc, AH[ks], bl0, bl1);
            }
            int gc = nc*128 + ntl*8 + cq;
            if (gr0 < NN) *(float2*)&g_qrel[(size_t)gr0*512 + gc] = make_float2(acc[0], acc[1]);
            if (gr1 < NN) *(float2*)&g_qrel[(size_t)gr1*512 + gc] = make_float2(acc[2], acc[3]);
        }
    }
}
// ---------- fused edge phase: warp/dst, 4-edge ILP, smem q ----------
__global__ __launch_bounds__(256,1) void k_edge(const float* __restrict__ pri) {
    __shared__ float sQ[8*512];
    __shared__ float spri[8];
    int tid = threadIdx.x, wid = tid>>5, lane = tid & 31;
    if (tid < 8) spri[tid] = pri[tid] * 0.125f;
    int d = blockIdx.x*8 + wid;
    if (d >= NN) { return; }
    float* q = sQ + wid*512;
    #pragma unroll
    for (int r = 0; r < 8; r++)
        *(float2*)&q[r*64 + lane*2] = *(const float2*)&g_qrel[(size_t)d*512 + r*64 + lane*2];
    __syncwarp();
    int rs = g_rowptr[d], re = g_rowptr[d+1];
    float m = -3.0e38f, s = 0.f;
    float2 b[8];
    #pragma unroll
    for (int r = 0; r < 8; r++) b[r] = make_float2(0.f,0.f);
    for (int p = rs; p < re; p += 4) {
        int sp[4], rr[4];
        float2 kv[4], vv[4];
        float part[4];
        #pragma unroll
        for (int j = 0; j < 4; j++) {
            int pj = (p+j < re) ? p+j : re-1;
            int pk = g_csr[pj];
            sp[j] = pk & 0xFFFFF; rr[j] = pk >> 20;
            kv[j] = *(const float2*)&g_knode[(size_t)sp[j]*64 + lane*2];
            float2 qs = *(const float2*)&q[rr[j]*64 + lane*2];
            part[j] = kv[j].x*qs.x + kv[j].y*qs.y;
        }
        #pragma unroll
        for (int off = 16; off; off >>= 1) {
            part[0] += __shfl_xor_sync(~0u, part[0], off);
            part[1] += __shfl_xor_sync(~0u, part[1], off);
            part[2] += __shfl_xor_sync(~0u, part[2], off);
            part[3] += __shfl_xor_sync(~0u, part[3], off);
        }
        #pragma unroll
        for (int j = 0; j < 4; j++)
            vv[j] = *(const float2*)&g_vnode[(size_t)sp[j]*64 + lane*2];
        int nvalid = re - p; if (nvalid > 4) nvalid = 4;
        #pragma unroll
        for (int j = 0; j < 4; j++) {
            if (j >= nvalid) break;
            float score = part[j] * spri[rr[j]];
            if (score > m) {
                float c = __expf(m - score);
                s *= c;
                #pragma unroll
                for (int u = 0; u < 8; u++) { b[u].x *= c; b[u].y *= c; }
                m = score;
            }
            float wgt = __expf(score - m);
            s += wgt;
            int rj = rr[j];
            #pragma unroll
            for (int u = 0; u < 8; u++) if (rj == u) { b[u].x += wgt*vv[j].x; b[u].y += wgt*vv[j].y; }
        }
    }
    float inv = 1.0f / (s + 1e-16f);
    #pragma unroll
    for (int r = 0; r < 8; r++) {
        float ox = b[r].x*inv, oy = b[r].y*inv;
        __nv_bfloat162 h2, l2;
        h2.x = __float2bfloat16_rn(ox); h2.y = __float2bfloat16_rn(oy);
        l2.x = __float2bfloat16_rn(ox - __bfloat162float(h2.x));
        l2.y = __float2bfloat16_rn(oy - __bfloat162float(h2.y));
        size_t o = (size_t)d*512 + r*64 + lane*2;
        *(__nv_bfloat162*)&g_bkH[o] = h2;
        *(__nv_bfloat162*)&g_bkL[o] = l2;
    }
}
// ---------- mma GEMM 2: aggM = bucket @ msgT ----------
__global__ __launch_bounds__(256,1) void mma_agg() {
    extern __shared__ __nv_bfloat16 sb[];
    __nv_bfloat16 *sAH = sb, *sAL = sb+9216, *sBH = sb+18432, *sBL = sb+23040;
    int tid = threadIdx.x, lane = tid & 31, w = tid >> 5;
    int base = blockIdx.x*128;
    int m0 = w*16, r = lane>>2, cq = (lane&3)*2;
    float acc[8][4];
    #pragma unroll
    for (int ntl = 0; ntl < 8; ntl++)
        #pragma unroll
        for (int j = 0; j < 4; j++) acc[ntl][j] = 0.f;
    for (int kp = 0; kp < 8; kp++) {
        if (kp) __syncthreads();
        for (int u = tid; u < 1024; u += 256) {
            int row = u>>3, q = u&7;
            int idx = base+row; if (idx > NN-1) idx = NN-1;
            size_t g = (size_t)idx*512 + kp*64 + q*8;
            *(uint4*)(sAH + row*72 + q*8) = *(const uint4*)(g_bkH + g);
            *(uint4*)(sAL + row*72 + q*8) = *(const uint4*)(g_bkL + g);
        }
        for (int u = tid; u < 512; u += 256) {
            int row = u>>3, q = u&7;
            size_t g = (size_t)row*512 + kp*64 + q*8;
            *(uint4*)(sBH + row*72 + q*8) = *(const uint4*)(g_msgTH + g);
            *(uint4*)(sBL + row*72 + q*8) = *(const uint4*)(g_msgTL + g);
        }
        __syncthreads();
        uint32_t AH[4][4], AL[4][4];
        #pragma unroll
        for (int ks = 0; ks < 4; ks++) {
            int c = ks*16 + cq;
            AH[ks][0] = *(const uint32_t*)(sAH + (m0+r  )*72 + c);
            AH[ks][1] = *(const uint32_t*)(sAH + (m0+r+8)*72 + c);
            AH[ks][2] = *(const uint32_t*)(sAH + (m0+r  )*72 + c + 8);
            AH[ks][3] = *(const uint32_t*)(sAH + (m0+r+8)*72 + c + 8);
            AL[ks][0] = *(const uint32_t*)(sAL + (m0+r  )*72 + c);
            AL[ks][1] = *(const uint32_t*)(sAL + (m0+r+8)*72 + c);
            AL[ks][2] = *(const uint32_t*)(sAL + (m0+r  )*72 + c + 8);
            AL[ks][3] = *(const uint32_t*)(sAL + (m0+r+8)*72 + c + 8);
        }
        #pragma unroll
        for (int ntl = 0; ntl < 8; ntl++) {
            int brow = ntl*8 + r;
            #pragma unroll
            for (int ks = 0; ks < 4; ks++) {
                int bc = ks*16 + cq;
                uint32_t bh0 = *(const uint32_t*)(sBH + brow*72 + bc);
                uint32_t bh1 = *(const uint32_t*)(sBH + brow*72 + bc + 8);
                uint32_t bl0 = *(const uint32_t*)(sBL + brow*72 + bc);
                uint32_t bl1 = *(const uint32_t*)(sBL + brow*72 + bc + 8);
                mma_bf16(acc[ntl], AH[ks], bh0, bh1);
                mma_bf16(acc[ntl], AL[ks], bh0, bh1);
                mma_bf16(acc[ntl], AH[ks], bl0, bl1);
            }
        }
    }
    int gr0 = base + m0 + r, gr1 = gr0 + 8;
    #pragma unroll
    for (int ntl = 0; ntl < 8; ntl++) {
        int gc = ntl*8 + cq;
        if (gr0 < NN) *(float2*)&g_aggM[(size_t)gr0*64 + gc] = make_float2(acc[ntl][0], acc[ntl][1]);
        if (gr1 < NN) *(float2*)&g_aggM[(size_t)gr1*64 + gc] = make_float2(acc[ntl][2], acc[ntl][3]);
    }
}
// ---------- typed final GEMM (FFMA): out = aggM @ aw[t] * sigmoid(skip[t]) ----------
__global__ __launch_bounds__(256,1) void k_outT(float* __restrict__ out, const float* __restrict__ aw,
                      const float* __restrict__ skipv, const void* nt) {
    extern __shared__ float sm[];
    float* sA = sm;
    float* sW = sA + 8192;
    int* sNode = (int*)(sW + 4096);
    int* sTy = sNode + 128;
    int tid = threadIdx.x, base = blockIdx.x*128;
    if (tid < 128) {
        int idx = base + tid; if (idx > NN-1) idx = NN-1;
        int node = g_perm[idx];
        sNode[tid] = node;
        sTy[tid] = ld_idx(nt, node, g_is64_nt);
    }
    __syncthreads();
    {
        int m = tid >> 1, half = tid & 1;
        int idx = base + m; if (idx > NN-1) idx = NN-1;
        const float4* hp = (const float4*)(g_aggM + (size_t)idx*64 + half*32);
        #pragma unroll
        for (int j = 0; j < 8; j++) {
            float4 v = hp[j]; int k0 = half*32 + j*4;
            sA[(k0+0)*128+m]=v.x; sA[(k0+1)*128+m]=v.y; sA[(k0+2)*128+m]=v.z; sA[(k0+3)*128+m]=v.w;
        }
    }
    __syncthreads();
    int t0 = sTy[0], t1 = sTy[127];
    int wy = tid >> 4, wx = tid & 15;
    int m0 = wy*8, c0 = wx*4;
    for (int t = t0; t <= t1; t++) {
        for (int e = tid; e < 1024; e += 256)
            ((float4*)sW)[e] = ((const float4*)(aw + t*4096))[e];
        __syncthreads();
        float acc[8][4];
        #pragma unroll
        for (int i = 0; i < 8; i++)
            #pragma unroll
            for (int j = 0; j < 4; j++) acc[i][j] = 0.f;
        #pragma unroll 4
        for (int k = 0; k < 64; k++) {
            float4 bw = *(const float4*)&sW[k*64+c0];
            float4 a0 = *(const float4*)&sA[k*128+m0];
            float4 a1 = *(const float4*)&sA[k*128+m0+4];
            float av[8] = {a0.x,a0.y,a0.z,a0.w,a1.x,a1.y,a1.z,a1.w};
            #pragma unroll
            for (int i = 0; i < 8; i++) {
                acc[i][0]+=av[i]*bw.x; acc[i][1]+=av[i]*bw.y; acc[i][2]+=av[i]*bw.z; acc[i][3]+=av[i]*bw.w;
            }
        }
        float sc = 1.0f / (1.0f + __expf(-skipv[t]));
        #pragma unroll
        for (int i = 0; i < 8; i++) {
            int row = m0 + i, idx = base + row;
            if (idx < NN && sTy[row] == t)
                *(float4*)&out[(size_t)sNode[row]*64+c0] =
                    make_float4(acc[i][0]*sc, acc[i][1]*sc, acc[i][2]*sc, acc[i][3]*sc);
        }
        __syncthreads();
    }
}

extern "C" void kernel_launch(void* const* d_in, const int* in_sizes, int n_in,
                              void* d_out, int out_size) {
    const float* h   = (const float*)d_in[0];
    const void*  adj = d_in[1];
    const void*  et  = d_in[2];
    const void*  nt  = d_in[3];
    int off = n_in - 8;
    const float* kw   = (const float*)d_in[off+0];
    const float* qw   = (const float*)d_in[off+1];
    const float* vw   = (const float*)d_in[off+2];
    const float* aw   = (const float*)d_in[off+3];
    const float* pri  = (const float*)d_in[off+4];
    const float* att  = (const float*)d_in[off+5];
    const float* msg  = (const float*)d_in[off+6];
    const float* skip = (const float*)d_in[off+7];
    float* out = (float*)d_out;

    const int SM_KVQ  = 46080*2 + 1024 + 64;  // bf16 area + meta
    const int SM_QREL = 4*9216*2;
    const int SM_AGG  = (2*9216 + 2*4608)*2;
    const int SM_OUT  = (8192 + 4096)*4 + 256*4 + 16;
    cudaFuncSetAttribute(mma_kvq,  cudaFuncAttributeMaxDynamicSharedMemorySize, SM_KVQ);
    cudaFuncSetAttribute(mma_qrel, cudaFuncAttributeMaxDynamicSharedMemorySize, SM_QREL);
    cudaFuncSetAttribute(mma_agg,  cudaFuncAttributeMaxDynamicSharedMemorySize, SM_AGG);
    cudaFuncSetAttribute(k_outT,   cudaFuncAttributeMaxDynamicSharedMemorySize, SM_OUT);

    k_detect<<<1,1>>>(adj, et, nt);
    k_zero<<<(NN+255)/256,256>>>();
    k_nhist<<<(NN+255)/256,256>>>(nt);
    k_tscan<<<1,1>>>();
    k_nscatter<<<(NN+255)/256,256>>>(nt);
    k_iperm<<<(NN+255)/256,256>>>();
    k_ehist<<<(EE+255)/256,256>>>(adj);
    k_scanA<<<NB_SCAN,256>>>();
    k_scanB<<<1,256>>>();
    k_scanC<<<NB_SCAN,256>>>();
    k_escatter<<<(EE+255)/256,256>>>(adj, et);
    k_cvt<<<128,256>>>(att, msg);
    k_cvtw<<<(3*TT*4096+255)/256,256>>>(kw, vw, qw);
    k_cvth<<<(NN*64+255)/256,256>>>(h);

    int nb = (NN + 127) / 128;
    mma_kvq<<<nb,256,SM_KVQ>>>(nt);
    mma_qrel<<<nb,256,SM_QREL>>>();
    k_edge<<<(NN+7)/8,256>>>(pri);
    mma_agg<<<nb,256,SM_AGG>>>();
    k_outT<<<nb,256,SM_OUT>>>(out, aw, skip, nt);
}

// round 7
// speedup vs baseline: 1.5795x; 1.0427x over previous
#include <cuda_runtime.h>
#include <cuda_bf16.h>
#include <stdint.h>

#define NN 50000
#define EE 800000
#define TT 8
#define NB_SCAN 196

__device__ int   g_is64_adj, g_is64_et, g_is64_nt;
__device__ float g_knode[(size_t)NN*64];
__device__ float g_vnode[(size_t)NN*64];
__device__ __nv_bfloat16 g_hH[(size_t)NN*64], g_hL[(size_t)NN*64];
__device__ __nv_bfloat16 g_qnH[(size_t)NN*64], g_qnL[(size_t)NN*64];
__device__ __nv_bfloat16 g_wTH[3*TT*4096], g_wTL[3*TT*4096];
__device__ __nv_bfloat16 g_attH[512*64], g_attL[512*64];   // scaled by pri[r]/8
__device__ __nv_bfloat16 g_msgTH[64*512], g_msgTL[64*512];
__device__ float g_qrel[(size_t)NN*512];
__device__ __nv_bfloat16 g_bkH[(size_t)NN*512], g_bkL[(size_t)NN*512];
__device__ float g_aggM[(size_t)NN*64];
__device__ int g_perm[NN], g_iperm[NN], g_deg[NN], g_cursor[NN], g_rowptr[NN+1];
__device__ int g_bsum[256], g_boff[256], g_tcount[TT], g_tbase[TT], g_tcur[TT];
__device__ int g_csr[EE];

__device__ __forceinline__ int ld_idx(const void* p, long i, int is64) {
    if (is64) return (int)(((const long long*)p)[i]);
    return ((const int*)p)[i];
}
__device__ __forceinline__ void mma_bf16(float* d, const uint32_t* a, uint32_t b0, uint32_t b1) {
    asm volatile("mma.sync.aligned.m16n8k16.row.col.f32.bf16.bf16.f32 "
        "{%0,%1,%2,%3},{%4,%5,%6,%7},{%8,%9},{%0,%1,%2,%3};"
        : "+f"(d[0]), "+f"(d[1]), "+f"(d[2]), "+f"(d[3])
        : "r"(a[0]), "r"(a[1]), "r"(a[2]), "r"(a[3]), "r"(b0), "r"(b1));
}

// ---------- plumbing ----------
__global__ void k_zero(const void* adj, const void* et, const void* nt) {
    int i = blockIdx.x*blockDim.x + threadIdx.x;
    if (i < NN) { g_deg[i]=0; g_cursor[i]=0; }
    if (i < TT) { g_tcount[i]=0; g_tcur[i]=0; }
    if (i == 0) {
        g_rowptr[NN] = EE;
        int a=1,b=1,c=1;
        for (int j=0;j<128;j++) if (((const int*)adj)[2*(j*1000)+1]) { a=0; break; }
        for (int j=0;j<128;j++) if (((const int*)et )[2*(j*3000)+1]) { b=0; break; }
        for (int j=0;j<128;j++) if (((const int*)nt )[2*(j*150 )+1]) { c=0; break; }
        g_is64_adj=a; g_is64_et=b; g_is64_nt=c;
    }
}
__global__ void k_nhist(const void* nt) {
    int i = blockIdx.x*blockDim.x + threadIdx.x;
    if (i < NN) atomicAdd(&g_tcount[ld_idx(nt,i,g_is64_nt)], 1);
}
__global__ void k_tscan() {
    if (threadIdx.x==0 && blockIdx.x==0) { int s=0; for (int t=0;t<TT;t++){ g_tbase[t]=s; s+=g_tcount[t]; } }
}
__global__ void k_nscatter(const void* nt) {
    int i = blockIdx.x*blockDim.x + threadIdx.x;
    if (i >= NN) return;
    int t = ld_idx(nt,i,g_is64_nt);
    int p = g_tbase[t] + atomicAdd(&g_tcur[t],1);
    g_perm[p] = i;
    g_iperm[i] = p;
}
__global__ void k_ehist(const void* adj) {
    int e = blockIdx.x*blockDim.x + threadIdx.x;
    if (e < EE) atomicAdd(&g_deg[g_iperm[ld_idx(adj,(long)EE+e,g_is64_adj)]], 1);
}
__global__ void k_scanA() {
    __shared__ int s[256];
    int i = blockIdx.x*256 + threadIdx.x;
    int v = (i < NN) ? g_deg[i] : 0;
    s[threadIdx.x] = v; __syncthreads();
    for (int off=1; off<256; off<<=1) {
        int t = (threadIdx.x>=off) ? s[threadIdx.x-off] : 0;
        __syncthreads(); s[threadIdx.x] += t; __syncthreads();
    }
    if (i < NN) g_rowptr[i] = s[threadIdx.x] - v;
    if (threadIdx.x == 255) g_bsum[blockIdx.x] = s[255];
}
__global__ void k_scanB() {
    __shared__ int s[256];
    int i = threadIdx.x;
    int v = (i < NB_SCAN) ? g_bsum[i] : 0;
    s[i] = v; __syncthreads();
    for (int off=1; off<256; off<<=1) {
        int t = (i>=off) ? s[i-off] : 0;
        __syncthreads(); s[i] += t; __syncthreads();
    }
    g_boff[i] = s[i] - v;
}
__global__ void k_scanC() {
    int i = blockIdx.x*256 + threadIdx.x;
    if (i < NN) g_rowptr[i] += g_boff[blockIdx.x];
}
__global__ void k_escatter(const void* adj, const void* et) {
    int e = blockIdx.x*blockDim.x + threadIdx.x;
    if (e >= EE) return;
    int src = ld_idx(adj, e, g_is64_adj);
    int dst = ld_idx(adj, (long)EE+e, g_is64_adj);
    int r   = ld_idx(et, e, g_is64_et);
    int dp = g_iperm[dst];
    g_csr[g_rowptr[dp] + atomicAdd(&g_cursor[dp],1)] = g_iperm[src] | (r << 20);
}
// ---------- all bf16 hi/lo conversions, one kernel ----------
#define CVT_W0 32768
#define CVT_W1 (32768 + 3*TT*4096)
#define CVT_END (CVT_W1 + NN*64)
__global__ void k_cvtall(const float* __restrict__ att, const float* __restrict__ msg,
                         const float* __restrict__ kw, const float* __restrict__ vw,
                         const float* __restrict__ qw, const float* __restrict__ h,
                         const float* __restrict__ pri) {
    int i = blockIdx.x*256 + threadIdx.x;
    if (i < CVT_W0) {
        float sc = pri[i >> 12] * 0.125f;     // fold pri/sqrt(D) into att
        float a = att[i] * sc;
        __nv_bfloat16 ah = __float2bfloat16_rn(a);
        g_attH[i] = ah; g_attL[i] = __float2bfloat16_rn(a - __bfloat162float(ah));
        float m = msg[i];
        int k = i >> 6, j = i & 63;
        __nv_bfloat16 mh = __float2bfloat16_rn(m);
        g_msgTH[j*512 + k] = mh;
        g_msgTL[j*512 + k] = __float2bfloat16_rn(m - __bfloat162float(mh));
    } else if (i < CVT_W1) {
        int u = i - CVT_W0;
        int mat = u >> 15, rem = u & 32767;
        int e = rem & 4095;
        int k = e >> 6, c = e & 63;
        const float* W = (mat == 0) ? kw : (mat == 1) ? vw : qw;
        float v = W[rem];
        __nv_bfloat16 vh = __float2bfloat16_rn(v);
        int o = u - e + c*64 + k;
        g_wTH[o] = vh; g_wTL[o] = __float2bfloat16_rn(v - __bfloat162float(vh));
    } else if (i < CVT_END) {
        int u = i - CVT_W1;
        float v = h[u];
        __nv_bfloat16 vh = __float2bfloat16_rn(v);
        g_hH[u] = vh; g_hL[u] = __float2bfloat16_rn(v - __bfloat162float(vh));
    }
}
// ---------- mma typed GEMM: knode/vnode fp32 + qn hi/lo ----------
__global__ __launch_bounds__(256,1) void mma_kvq(const void* nt) {
    extern __shared__ __nv_bfloat16 sb[];
    __nv_bfloat16 *sAH = sb, *sAL = sb+9216;
    __nv_bfloat16 *sBH = sb+18432, *sBL = sb+18432+13824;
    int* sNode = (int*)(sb + 46080);
    int* sTy = sNode + 128;
    int tid = threadIdx.x, lane = tid & 31, w = tid >> 5;
    int base = blockIdx.x*128;
    if (tid < 128) {
        int idx = base + tid; if (idx > NN-1) idx = NN-1;
        int node = g_perm[idx];
        sNode[tid] = node;
        sTy[tid] = ld_idx(nt, node, g_is64_nt);
    }
    __syncthreads();
    for (int u = tid; u < 1024; u += 256) {
        int row = u>>3, q = u&7;
        size_t g = (size_t)sNode[row]*64 + q*8;
        *(uint4*)(sAH + row*72 + q*8) = *(const uint4*)(g_hH + g);
        *(uint4*)(sAL + row*72 + q*8) = *(const uint4*)(g_hL + g);
    }
    __syncthreads();
    int m0 = w*16, r = lane>>2, cq = (lane&3)*2;
    uint32_t AH[4][4], AL[4][4];
    #pragma unroll
    for (int ks = 0; ks < 4; ks++) {
        int c = ks*16 + cq;
        AH[ks][0] = *(const uint32_t*)(sAH + (m0+r  )*72 + c);
        AH[ks][1] = *(const uint32_t*)(sAH + (m0+r+8)*72 + c);
        AH[ks][2] = *(const uint32_t*)(sAH + (m0+r  )*72 + c + 8);
        AH[ks][3] = *(const uint32_t*)(sAH + (m0+r+8)*72 + c + 8);
        AL[ks][0] = *(const uint32_t*)(sAL + (m0+r  )*72 + c);
        AL[ks][1] = *(const uint32_t*)(sAL + (m0+r+8)*72 + c);
        AL[ks][2] = *(const uint32_t*)(sAL + (m0+r  )*72 + c + 8);
        AL[ks][3] = *(const uint32_t*)(sAL + (m0+r+8)*72 + c + 8);
    }
    int t0 = sTy[0], t1 = sTy[127];
    int gr0 = base + m0 + r, gr1 = gr0 + 8;
    int row0 = m0 + r, row1 = row0 + 8;
    for (int t = t0; t <= t1; t++) {
        if (t > t0) __syncthreads();
        for (int u = tid; u < 1536; u += 256) {
            int mat = u >> 9, e = u & 511;
            int row = e>>3, q = e&7;
            size_t g = (size_t)(mat*TT + t)*4096 + row*64 + q*8;
            *(uint4*)(sBH + mat*4608 + row*72 + q*8) = *(const uint4*)(g_wTH + g);
            *(uint4*)(sBL + mat*4608 + row*72 + q*8) = *(const uint4*)(g_wTL + g);
        }
        __syncthreads();
        bool ok0 = (gr0 < NN) && (sTy[row0] == t);
        bool ok1 = (gr1 < NN) && (sTy[row1] == t);
        #pragma unroll
        for (int mat = 0; mat < 3; mat++) {
            const __nv_bfloat16 *BH = sBH + mat*4608, *BL = sBL + mat*4608;
            #pragma unroll
            for (int ntl = 0; ntl < 8; ntl++) {
                float acc[4] = {0.f,0.f,0.f,0.f};
                int brow = ntl*8 + r;
                #pragma unroll
                for (int ks = 0; ks < 4; ks++) {
                    int bc = ks*16 + cq;
                    uint32_t bh0 = *(const uint32_t*)(BH + brow*72 + bc);
                    uint32_t bh1 = *(const uint32_t*)(BH + brow*72 + bc + 8);
                    uint32_t bl0 = *(const uint32_t*)(BL + brow*72 + bc);
                    uint32_t bl1 = *(const uint32_t*)(BL + brow*72 + bc + 8);
                    mma_bf16(acc, AH[ks], bh0, bh1);
                    mma_bf16(acc, AL[ks], bh0, bh1);
                    mma_bf16(acc, AH[ks], bl0, bl1);
                }
                int gc = ntl*8 + cq;
                if (mat == 0) {
                    if (ok0) *(float2*)&g_knode[(size_t)gr0*64+gc] = make_float2(acc[0],acc[1]);
                    if (ok1) *(float2*)&g_knode[(size_t)gr1*64+gc] = make_float2(acc[2],acc[3]);
                } else if (mat == 1) {
                    if (ok0) *(float2*)&g_vnode[(size_t)gr0*64+gc] = make_float2(acc[0],acc[1]);
                    if (ok1) *(float2*)&g_vnode[(size_t)gr1*64+gc] = make_float2(acc[2],acc[3]);
                } else {
                    if (ok0) {
                        __nv_bfloat162 h2,l2;
                        h2.x=__float2bfloat16_rn(acc[0]); h2.y=__float2bfloat16_rn(acc[1]);
                        l2.x=__float2bfloat16_rn(acc[0]-__bfloat162float(h2.x));
                        l2.y=__float2bfloat16_rn(acc[1]-__bfloat162float(h2.y));
                        size_t o = (size_t)gr0*64+gc;
                        *(__nv_bfloat162*)&g_qnH[o]=h2; *(__nv_bfloat162*)&g_qnL[o]=l2;
                    }
                    if (ok1) {
                        __nv_bfloat162 h2,l2;
                        h2.x=__float2bfloat16_rn(acc[2]); h2.y=__float2bfloat16_rn(acc[3]);
                        l2.x=__float2bfloat16_rn(acc[2]-__bfloat162float(h2.x));
                        l2.y=__float2bfloat16_rn(acc[3]-__bfloat162float(h2.y));
                        size_t o = (size_t)gr1*64+gc;
                        *(__nv_bfloat162*)&g_qnH[o]=h2; *(__nv_bfloat162*)&g_qnL[o]=l2;
                    }
                }
            }
        }
    }
}
// ---------- mma GEMM 1: qrel[128,512] = qn @ att^T ----------
__global__ __launch_bounds__(256,1) void mma_qrel() {
    extern __shared__ __nv_bfloat16 sb[];
    __nv_bfloat16 *sAH = sb, *sAL = sb+9216, *sBH = sb+18432, *sBL = sb+27648;
    int tid = threadIdx.x, lane = tid & 31, w = tid >> 5;
    int base = blockIdx.x*128;
    for (int u = tid; u < 1024; u += 256) {
        int row = u>>3, q = u&7;
        int idx = base+row; if (idx > NN-1) idx = NN-1;
        *(uint4*)(sAH + row*72 + q*8) = *(const uint4*)(g_qnH + (size_t)idx*64 + q*8);
        *(uint4*)(sAL + row*72 + q*8) = *(const uint4*)(g_qnL + (size_t)idx*64 + q*8);
    }
    __syncthreads();
    int m0 = w*16, r = lane>>2, cq = (lane&3)*2;
    uint32_t AH[4][4], AL[4][4];
    #pragma unroll
    for (int ks = 0; ks < 4; ks++) {
        int c = ks*16 + cq;
        AH[ks][0] = *(const uint32_t*)(sAH + (m0+r  )*72 + c);
        AH[ks][1] = *(const uint32_t*)(sAH + (m0+r+8)*72 + c);
        AH[ks][2] = *(const uint32_t*)(sAH + (m0+r  )*72 + c + 8);
        AH[ks][3] = *(const uint32_t*)(sAH + (m0+r+8)*72 + c + 8);
        AL[ks][0] = *(const uint32_t*)(sAL + (m0+r  )*72 + c);
        AL[ks][1] = *(const uint32_t*)(sAL + (m0+r+8)*72 + c);
        AL[ks][2] = *(const uint32_t*)(sAL + (m0+r  )*72 + c + 8);
        AL[ks][3] = *(const uint32_t*)(sAL + (m0+r+8)*72 + c + 8);
    }
    int gr0 = base + m0 + r, gr1 = gr0 + 8;
    for (int nc = 0; nc < 4; nc++) {
        if (nc) __syncthreads();
        for (int u = tid; u < 1024; u += 256) {
            int row = u>>3, q = u&7;
            *(uint4*)(sBH + row*72 + q*8) = *(const uint4*)(g_attH + (size_t)(nc*128+row)*64 + q*8);
            *(uint4*)(sBL + row*72 + q*8) = *(const uint4*)(g_attL + (size_t)(nc*128+row)*64 + q*8);
        }
        __syncthreads();
        #pragma unroll 4
        for (int ntl = 0; ntl < 16; ntl++) {
            float acc[4] = {0.f, 0.f, 0.f, 0.f};
            int brow = ntl*8 + r;
            #pragma unroll
            for (int ks = 0; ks < 4; ks++) {
                int bc = ks*16 + cq;
                uint32_t bh0 = *(const uint32_t*)(sBH + brow*72 + bc);
                uint32_t bh1 = *(const uint32_t*)(sBH + brow*72 + bc + 8);
                uint32_t bl0 = *(const uint32_t*)(sBL + brow*72 + bc);
                uint32_t bl1 = *(const uint32_t*)(sBL + brow*72 + bc + 8);
                mma_bf16(acc, AH[ks], bh0, bh1);
                mma_bf16(acc, AL[ks], bh0, bh1);
                mma_bf16(acc, AH[ks], bl0, bl1);
            }
            int gc = nc*128 + ntl*8 + cq;
            if (gr0 < NN) *(float2*)&g_qrel[(size_t)gr0*512 + gc] = make_float2(acc[0], acc[1]);
            if (gr1 < NN) *(float2*)&g_qrel[(size_t)gr1*512 + gc] = make_float2(acc[2], acc[3]);
        }
    }
}
// ---------- fused edge phase: deferred batch-max online softmax ----------
__global__ __launch_bounds__(256,1) void k_edge() {
    __shared__ float sQ[8*512];
    int tid = threadIdx.x, wid = tid>>5, lane = tid & 31;
    int d = blockIdx.x*8 + wid;
    if (d >= NN) return;
    float* q = sQ + wid*512;
    #pragma unroll
    for (int r = 0; r < 8; r++)
        *(float2*)&q[r*64 + lane*2] = *(const float2*)&g_qrel[(size_t)d*512 + r*64 + lane*2];
    __syncwarp();
    int rs = g_rowptr[d], re = g_rowptr[d+1];
    float m = -3.0e38f, s = 0.f;
    float2 b[8];
    #pragma unroll
    for (int r = 0; r < 8; r++) b[r] = make_float2(0.f,0.f);
    for (int p = rs; p < re; p += 4) {
        int sp[4], rr[4];
        float2 vv[4];
        float sc[4];
        #pragma unroll
        for (int j = 0; j < 4; j++) {
            int pj = (p+j < re) ? p+j : re-1;
            int pk = g_csr[pj];
            sp[j] = pk & 0xFFFFF; rr[j] = pk >> 20;
            float2 kv = *(const float2*)&g_knode[(size_t)sp[j]*64 + lane*2];
            float2 qs = *(const float2*)&q[rr[j]*64 + lane*2];
            sc[j] = kv.x*qs.x + kv.y*qs.y;
        }
        #pragma unroll
        for (int off = 16; off; off >>= 1) {
            sc[0] += __shfl_xor_sync(~0u, sc[0], off);
            sc[1] += __shfl_xor_sync(~0u, sc[1], off);
            sc[2] += __shfl_xor_sync(~0u, sc[2], off);
            sc[3] += __shfl_xor_sync(~0u, sc[3], off);
        }
        #pragma unroll
        for (int j = 0; j < 4; j++) {
            vv[j] = *(const float2*)&g_vnode[(size_t)sp[j]*64 + lane*2];
            if (p+j >= re) sc[j] = -3.0e38f;
        }
        float bmax = fmaxf(fmaxf(sc[0], sc[1]), fmaxf(sc[2], sc[3]));
        if (bmax > m) {
            float c = __expf(m - bmax);
            s *= c;
            #pragma unroll
            for (int u = 0; u < 8; u++) { b[u].x *= c; b[u].y *= c; }
            m = bmax;
        }
        float w0 = __expf(sc[0]-m), w1 = __expf(sc[1]-m);
        float w2 = __expf(sc[2]-m), w3 = __expf(sc[3]-m);
        s += (w0+w1) + (w2+w3);
        float wj[4] = {w0, w1, w2, w3};
        #pragma unroll
        for (int j = 0; j < 4; j++) {
            int rj = rr[j];
            #pragma unroll
            for (int u = 0; u < 8; u++)
                if (rj == u) { b[u].x += wj[j]*vv[j].x; b[u].y += wj[j]*vv[j].y; }
        }
    }
    float inv = 1.0f / (s + 1e-16f);
    #pragma unroll
    for (int r = 0; r < 8; r++) {
        float ox = b[r].x*inv, oy = b[r].y*inv;
        __nv_bfloat162 h2, l2;
        h2.x = __float2bfloat16_rn(ox); h2.y = __float2bfloat16_rn(oy);
        l2.x = __float2bfloat16_rn(ox - __bfloat162float(h2.x));
        l2.y = __float2bfloat16_rn(oy - __bfloat162float(h2.y));
        size_t o = (size_t)d*512 + r*64 + lane*2;
        *(__nv_bfloat162*)&g_bkH[o] = h2;
        *(__nv_bfloat162*)&g_bkL[o] = l2;
    }
}
// ---------- mma GEMM 2: aggM = bucket @ msgT ----------
__global__ __launch_bounds__(256,1) void mma_agg() {
    extern __shared__ __nv_bfloat16 sb[];
    __nv_bfloat16 *sAH = sb, *sAL = sb+9216, *sBH = sb+18432, *sBL = sb+23040;
    int tid = threadIdx.x, lane = tid & 31, w = tid >> 5;
    int base = blockIdx.x*128;
    int m0 = w*16, r = lane>>2, cq = (lane&3)*2;
    float acc[8][4];
    #pragma unroll
    for (int ntl = 0; ntl < 8; ntl++)
        #pragma unroll
        for (int j = 0; j < 4; j++) acc[ntl][j] = 0.f;
    for (int kp = 0; kp < 8; kp++) {
        if (kp) __syncthreads();
        for (int u = tid; u < 1024; u += 256) {
            int row = u>>3, q = u&7;
            int idx = base+row; if (idx > NN-1) idx = NN-1;
            size_t g = (size_t)idx*512 + kp*64 + q*8;
            *(uint4*)(sAH + row*72 + q*8) = *(const uint4*)(g_bkH + g);
            *(uint4*)(sAL + row*72 + q*8) = *(const uint4*)(g_bkL + g);
        }
        for (int u = tid; u < 512; u += 256) {
            int row = u>>3, q = u&7;
            size_t g = (size_t)row*512 + kp*64 + q*8;
            *(uint4*)(sBH + row*72 + q*8) = *(const uint4*)(g_msgTH + g);
            *(uint4*)(sBL + row*72 + q*8) = *(const uint4*)(g_msgTL + g);
        }
        __syncthreads();
        uint32_t AH[4][4], AL[4][4];
        #pragma unroll
        for (int ks = 0; ks < 4; ks++) {
            int c = ks*16 + cq;
            AH[ks][0] = *(const uint32_t*)(sAH + (m0+r  )*72 + c);
            AH[ks][1] = *(const uint32_t*)(sAH + (m0+r+8)*72 + c);
            AH[ks][2] = *(const uint32_t*)(sAH + (m0+r  )*72 + c + 8);
            AH[ks][3] = *(const uint32_t*)(sAH + (m0+r+8)*72 + c + 8);
            AL[ks][0] = *(const uint32_t*)(sAL + (m0+r  )*72 + c);
            AL[ks][1] = *(const uint32_t*)(sAL + (m0+r+8)*72 + c);
            AL[ks][2] = *(const uint32_t*)(sAL + (m0+r  )*72 + c + 8);
            AL[ks][3] = *(const uint32_t*)(sAL + (m0+r+8)*72 + c + 8);
        }
        #pragma unroll
        for (int ntl = 0; ntl < 8; ntl++) {
            int brow = ntl*8 + r;
            #pragma unroll
            for (int ks = 0; ks < 4; ks++) {
                int bc = ks*16 + cq;
                uint32_t bh0 = *(const uint32_t*)(sBH + brow*72 + bc);
                uint32_t bh1 = *(const uint32_t*)(sBH + brow*72 + bc + 8);
                uint32_t bl0 = *(const uint32_t*)(sBL + brow*72 + bc);
                uint32_t bl1 = *(const uint32_t*)(sBL + brow*72 + bc + 8);
                mma_bf16(acc[ntl], AH[ks], bh0, bh1);
                mma_bf16(acc[ntl], AL[ks], bh0, bh1);
                mma_bf16(acc[ntl], AH[ks], bl0, bl1);
            }
        }
    }
    int gr0 = base + m0 + r, gr1 = gr0 + 8;
    #pragma unroll
    for (int ntl = 0; ntl < 8; ntl++) {
        int gc = ntl*8 + cq;
        if (gr0 < NN) *(float2*)&g_aggM[(size_t)gr0*64 + gc] = make_float2(acc[ntl][0], acc[ntl][1]);
        if (gr1 < NN) *(float2*)&g_aggM[(size_t)gr1*64 + gc] = make_float2(acc[ntl][2], acc[ntl][3]);
    }
}
// ---------- typed final GEMM (FFMA) ----------
__global__ __launch_bounds__(256,1) void k_outT(float* __restrict__ out, const float* __restrict__ aw,
                      const float* __restrict__ skipv, const void* nt) {
    extern __shared__ float sm[];
    float* sA = sm;
    float* sW = sA + 8192;
    int* sNode = (int*)(sW + 4096);
    int* sTy = sNode + 128;
    int tid = threadIdx.x, base = blockIdx.x*128;
    if (tid < 128) {
        int idx = base + tid; if (idx > NN-1) idx = NN-1;
        int node = g_perm[idx];
        sNode[tid] = node;
        sTy[tid] = ld_idx(nt, node, g_is64_nt);
    }
    __syncthreads();
    {
        int m = tid >> 1, half = tid & 1;
        int idx = base + m; if (idx > NN-1) idx = NN-1;
        const float4* hp = (const float4*)(g_aggM + (size_t)idx*64 + half*32);
        #pragma unroll
        for (int j = 0; j < 8; j++) {
            float4 v = hp[j]; int k0 = half*32 + j*4;
            sA[(k0+0)*128+m]=v.x; sA[(k0+1)*128+m]=v.y; sA[(k0+2)*128+m]=v.z; sA[(k0+3)*128+m]=v.w;
        }
    }
    __syncthreads();
    int t0 = sTy[0], t1 = sTy[127];
    int wy = tid >> 4, wx = tid & 15;
    int m0 = wy*8, c0 = wx*4;
    for (int t = t0; t <= t1; t++) {
        for (int e = tid; e < 1024; e += 256)
            ((float4*)sW)[e] = ((const float4*)(aw + t*4096))[e];
        __syncthreads();
        float acc[8][4];
        #pragma unroll
        for (int i = 0; i < 8; i++)
            #pragma unroll
            for (int j = 0; j < 4; j++) acc[i][j] = 0.f;
        #pragma unroll 4
        for (int k = 0; k < 64; k++) {
            float4 bw = *(const float4*)&sW[k*64+c0];
            float4 a0 = *(const float4*)&sA[k*128+m0];
            float4 a1 = *(const float4*)&sA[k*128+m0+4];
            float av[8] = {a0.x,a0.y,a0.z,a0.w,a1.x,a1.y,a1.z,a1.w};
            #pragma unroll
            for (int i = 0; i < 8; i++) {
                acc[i][0]+=av[i]*bw.x; acc[i][1]+=av[i]*bw.y; acc[i][2]+=av[i]*bw.z; acc[i][3]+=av[i]*bw.w;
            }
        }
        float sc = 1.0f / (1.0f + __expf(-skipv[t]));
        #pragma unroll
        for (int i = 0; i < 8; i++) {
            int row = m0 + i, idx = base + row;
            if (idx < NN && sTy[row] == t)
                *(float4*)&out[(size_t)sNode[row]*64+c0] =
                    make_float4(acc[i][0]*sc, acc[i][1]*sc, acc[i][2]*sc, acc[i][3]*sc);
        }
        __syncthreads();
    }
}

extern "C" void kernel_launch(void* const* d_in, const int* in_sizes, int n_in,
                              void* d_out, int out_size) {
    const float* h   = (const float*)d_in[0];
    const void*  adj = d_in[1];
    const void*  et  = d_in[2];
    const void*  nt  = d_in[3];
    int off = n_in - 8;
    const float* kw   = (const float*)d_in[off+0];
    const float* qw   = (const float*)d_in[off+1];
    const float* vw   = (const float*)d_in[off+2];
    const float* aw   = (const float*)d_in[off+3];
    const float* pri  = (const float*)d_in[off+4];
    const float* att  = (const float*)d_in[off+5];
    const float* msg  = (const float*)d_in[off+6];
    const float* skip = (const float*)d_in[off+7];
    float* out = (float*)d_out;

    const int SM_KVQ  = 46080*2 + 1024 + 64;
    const int SM_QREL = 4*9216*2;
    const int SM_AGG  = (2*9216 + 2*4608)*2;
    const int SM_OUT  = (8192 + 4096)*4 + 256*4 + 16;
    cudaFuncSetAttribute(mma_kvq,  cudaFuncAttributeMaxDynamicSharedMemorySize, SM_KVQ);
    cudaFuncSetAttribute(mma_qrel, cudaFuncAttributeMaxDynamicSharedMemorySize, SM_QREL);
    cudaFuncSetAttribute(mma_agg,  cudaFuncAttributeMaxDynamicSharedMemorySize, SM_AGG);
    cudaFuncSetAttribute(k_outT,   cudaFuncAttributeMaxDynamicSharedMemorySize, SM_OUT);

    k_zero<<<(NN+255)/256,256>>>(adj, et, nt);
    k_nhist<<<(NN+255)/256,256>>>(nt);
    k_tscan<<<1,1>>>();
    k_nscatter<<<(NN+255)/256,256>>>(nt);
    k_ehist<<<(EE+255)/256,256>>>(adj);
    k_scanA<<<NB_SCAN,256>>>();
    k_scanB<<<1,256>>>();
    k_scanC<<<NB_SCAN,256>>>();
    k_escatter<<<(EE+255)/256,256>>>(adj, et);
    k_cvtall<<<(CVT_END+255)/256,256>>>(att, msg, kw, vw, qw, h, pri);

    int nb = (NN + 127) / 128;
    mma_kvq<<<nb,256,SM_KVQ>>>(nt);
    mma_qrel<<<nb,256,SM_QREL>>>();
    k_edge<<<(NN+7)/8,256>>>();
    mma_agg<<<nb,256,SM_AGG>>>();
    k_outT<<<nb,256,SM_OUT>>>(out, aw, skip, nt);
}